// round 1
// baseline (speedup 1.0000x reference)
#include <cuda_runtime.h>
#include <math.h>

// ---------------- problem constants (fixed-shape problem) ----------------
#define NMAX   50000
#define WD     256          // heads*Hd for layers 0/1
#define HDIM   64

// ---------------- scratch (no allocations allowed) ----------------
__device__ float  g_h  [(size_t)NMAX * WD];   // GEMM output  h = x @ W
__device__ float  g_out[(size_t)NMAX * WD];   // aggregated output (then bn'd in place)
__device__ float  g_s  [NMAX * 4];
__device__ float  g_d  [NMAX * 4];
__device__ float  g_m  [NMAX * 4];
__device__ float  g_den[NMAX * 4];
__device__ double g_bnsum[WD];
__device__ double g_bnsq [WD];
__device__ float  g_scale[WD];
__device__ float  g_shift[WD];
__device__ double g_pool_sum[HDIM];
__device__ int    g_pool_max[HDIM];
__device__ int    g_is64;

// ---------------- helpers ----------------
__device__ __forceinline__ void get_edge(const void* ei, int e, int E, int& s, int& d) {
    if (e >= E) { s = d = e - E; return; }          // self-loops appended
    if (g_is64) {
        const long long* p = (const long long*)ei;
        s = (int)p[e]; d = (int)p[(size_t)E + e];
    } else {
        const int* p = (const int*)ei;
        s = p[e]; d = p[E + e];
    }
}

__device__ __forceinline__ void atomicMaxF(float* addr, float val) {
    int old = __float_as_int(*addr);
    while (__int_as_float(old) < val) {
        int assumed = old;
        old = atomicCAS((int*)addr, assumed, __float_as_int(val));
        if (old == assumed) break;
    }
}

// detect int32 vs int64 edge_index on device (keeps launch graph static)
__global__ void detect_kernel(const void* ei) {
    if (threadIdx.x == 0 && blockIdx.x == 0) {
        const unsigned* w = (const unsigned*)ei;
        int is64 = 1;
        for (int i = 0; i < 8; i++)
            if (w[2 * i + 1] != 0u) is64 = 0;   // int64 values < 2^31 -> high words zero
        g_is64 = is64;
    }
}

// ---------------- SGEMM: C(g_h) = A[MxK] @ B[KxNc], 64x64 tile, 4x4/thread ----------------
__global__ __launch_bounds__(256) void sgemm64(const float* __restrict__ A,
                                               const float* __restrict__ B,
                                               int M, int K, int Nc) {
    __shared__ float As[16][65];
    __shared__ float Bs[16][64];
    int tid  = threadIdx.x;
    int brow = blockIdx.y, bcol = blockIdx.x;
    int tr = tid >> 4;            // 0..15
    int tc = tid & 15;            // 0..15
    int a_row = tid >> 2;         // 0..63
    int a_col = (tid & 3) << 2;   // 0,4,8,12
    int b_row = tid >> 4;         // 0..15
    int b_col = (tid & 15) << 2;  // 0..60
    int grow = brow * 64;
    float acc[4][4] = {};

    for (int k0 = 0; k0 < K; k0 += 16) {
        float4 av = make_float4(0.f, 0.f, 0.f, 0.f);
        if (grow + a_row < M)
            av = *(const float4*)&A[(size_t)(grow + a_row) * K + k0 + a_col];
        float4 bv = *(const float4*)&B[(size_t)(k0 + b_row) * Nc + bcol * 64 + b_col];
        As[a_col + 0][a_row] = av.x;
        As[a_col + 1][a_row] = av.y;
        As[a_col + 2][a_row] = av.z;
        As[a_col + 3][a_row] = av.w;
        *(float4*)&Bs[b_row][b_col] = bv;
        __syncthreads();
#pragma unroll
        for (int kk = 0; kk < 16; kk++) {
            float a[4], b[4];
#pragma unroll
            for (int i = 0; i < 4; i++) a[i] = As[kk][tr * 4 + i];
#pragma unroll
            for (int j = 0; j < 4; j++) b[j] = Bs[kk][tc * 4 + j];
#pragma unroll
            for (int i = 0; i < 4; i++)
#pragma unroll
                for (int j = 0; j < 4; j++) acc[i][j] += a[i] * b[j];
        }
        __syncthreads();
    }
#pragma unroll
    for (int i = 0; i < 4; i++) {
        int r = grow + tr * 4 + i;
        if (r < M) {
            float4 v = make_float4(acc[i][0], acc[i][1], acc[i][2], acc[i][3]);
            *(float4*)&g_h[(size_t)r * Nc + bcol * 64 + tc * 4] = v;
        }
    }
}

// ---------------- per-layer init: zero aggregate, reset softmax state ----------------
__global__ void init_layer(int total, int nh) {
    int stride = gridDim.x * blockDim.x;
    for (int i = blockIdx.x * blockDim.x + threadIdx.x; i < total; i += stride)
        g_out[i] = 0.f;
    for (int i = blockIdx.x * blockDim.x + threadIdx.x; i < nh; i += stride) {
        g_m[i]   = -1e30f;
        g_den[i] = 0.f;
    }
}

// ---------------- s/d attention logits: warp per node ----------------
template <int H>
__global__ void sd_kernel(const float* __restrict__ asrc, const float* __restrict__ adst, int N) {
    const int T = H * 64;
    int warp = (blockIdx.x * blockDim.x + threadIdx.x) >> 5;
    int lane = threadIdx.x & 31;
    if (warp >= N) return;
    float as[H], ad[H];
#pragma unroll
    for (int h = 0; h < H; h++) { as[h] = 0.f; ad[h] = 0.f; }
    for (int idx = lane; idx < T; idx += 32) {
        float hv = g_h[(size_t)warp * T + idx];
        int hd = idx >> 6;
        as[hd] += hv * asrc[idx];
        ad[hd] += hv * adst[idx];
    }
#pragma unroll
    for (int h = 0; h < H; h++) {
        float a = as[h], d = ad[h];
        for (int o = 16; o; o >>= 1) {
            a += __shfl_xor_sync(0xffffffffu, a, o);
            d += __shfl_xor_sync(0xffffffffu, d, o);
        }
        if (lane == 0) { g_s[warp * H + h] = a; g_d[warp * H + h] = d; }
    }
}

// ---------------- edge pass 1: segment max ----------------
template <int H>
__global__ void edge_max(const void* __restrict__ ei, int E, int ET) {
    int e = blockIdx.x * blockDim.x + threadIdx.x;
    if (e >= ET) return;
    int s, d; get_edge(ei, e, E, s, d);
#pragma unroll
    for (int h = 0; h < H; h++) {
        float v = g_s[s * H + h] + g_d[d * H + h];
        v = v > 0.f ? v : 0.2f * v;
        atomicMaxF(&g_m[d * H + h], v);
    }
}

// ---------------- edge pass 2: segment sum of exp ----------------
template <int H>
__global__ void edge_den(const void* __restrict__ ei, int E, int ET) {
    int e = blockIdx.x * blockDim.x + threadIdx.x;
    if (e >= ET) return;
    int s, d; get_edge(ei, e, E, s, d);
#pragma unroll
    for (int h = 0; h < H; h++) {
        float v = g_s[s * H + h] + g_d[d * H + h];
        v = v > 0.f ? v : 0.2f * v;
        atomicAdd(&g_den[d * H + h], expf(v - g_m[d * H + h]));
    }
}

// ---------------- edge pass 3: aggregation, warp per edge, v4 reductions ----------------
template <int H>
__global__ void edge_agg(const void* __restrict__ ei, int E, int ET) {
    const int T = H * 64;
    int gt = blockIdx.x * blockDim.x + threadIdx.x;
    int e = gt >> 5, lane = gt & 31;
    if (e >= ET) return;
    int s, d; get_edge(ei, e, E, s, d);
    float alpha[H];
#pragma unroll
    for (int h = 0; h < H; h++) {
        float v = g_s[s * H + h] + g_d[d * H + h];
        v = v > 0.f ? v : 0.2f * v;
        alpha[h] = expf(v - g_m[d * H + h]) / (g_den[d * H + h] + 1e-16f);
    }
#pragma unroll
    for (int j = 0; j < (T + 127) / 128; j++) {
        int c = (j * 32 + lane) * 4;
        if (c < T) {
            float4 hv = *(const float4*)&g_h[(size_t)s * T + c];
            float a = alpha[c >> 6];
            float* dst = &g_out[(size_t)d * T + c];
            asm volatile("red.global.add.v4.f32 [%0], {%1, %2, %3, %4};"
                         :: "l"(dst), "f"(hv.x * a), "f"(hv.y * a), "f"(hv.z * a), "f"(hv.w * a)
                         : "memory");
        }
    }
}

// ---------------- batchnorm ----------------
__global__ void bn_init() {
    int c = threadIdx.x;
    g_bnsum[c] = 0.0; g_bnsq[c] = 0.0;
}

__global__ void bn_stats(const float* __restrict__ bias, int C, int N) {
    int rpb = 256 / C;                 // rows touched per block iteration
    int c  = threadIdx.x % C;
    int r0 = blockIdx.x * rpb + threadIdx.x / C;
    double s = 0.0, q = 0.0;
    for (int r = r0; r < N; r += gridDim.x * rpb) {
        float v = g_out[(size_t)r * C + c] + bias[c];
        s += v; q += (double)v * v;
    }
    atomicAdd(&g_bnsum[c], s);
    atomicAdd(&g_bnsq[c], q);
}

__global__ void bn_final(const float* __restrict__ gamma, const float* __restrict__ beta,
                         int C, float inv_n) {
    int c = threadIdx.x;
    if (c >= C) return;
    float mu  = (float)(g_bnsum[c] * inv_n);
    float var = (float)(g_bnsq[c] * inv_n) - mu * mu;
    float sc  = gamma[c] * rsqrtf(var + 1e-5f);
    g_scale[c] = sc;
    g_shift[c] = beta[c] - sc * mu;
}

__global__ void bn_apply(const float* __restrict__ bias, int C, int total) {
    int stride = gridDim.x * blockDim.x;
    for (int i = blockIdx.x * blockDim.x + threadIdx.x; i < total; i += stride) {
        int c = i & (C - 1);
        float v = g_out[i] + bias[c];
        v = g_scale[c] * v + g_shift[c];
        g_out[i] = fmaxf(v, 0.f);
    }
}

// ---------------- global pooling over N ----------------
__global__ void pool_init() {
    int c = threadIdx.x;
    g_pool_sum[c] = 0.0;
    g_pool_max[c] = 0;          // values are post-ReLU (>= 0); bits(0.f)=0
}

__global__ void pool_kernel(int N) {
    __shared__ double ss[64];
    __shared__ int    sm[64];
    int t = threadIdx.x;
    if (t < 64) { ss[t] = 0.0; sm[t] = 0; }
    __syncthreads();
    int c  = t & 63;
    int r0 = blockIdx.x * 4 + (t >> 6);
    double ls = 0.0; float lm = 0.f;
    for (int r = r0; r < N; r += gridDim.x * 4) {
        float v = g_out[(size_t)r * 64 + c];
        ls += v; lm = fmaxf(lm, v);
    }
    atomicAdd(&ss[c], ls);
    atomicMax(&sm[c], __float_as_int(lm));
    __syncthreads();
    if (t < 64) {
        atomicAdd(&g_pool_sum[t], ss[t]);
        atomicMax(&g_pool_max[t], sm[t]);
    }
}

// ---------------- classifier head ----------------
__global__ void classifier(const float* __restrict__ Wc1, const float* __restrict__ bc1,
                           const float* __restrict__ Wc2, const float* __restrict__ bc2,
                           float* __restrict__ out, int N) {
    __shared__ float pooled[128];
    __shared__ float z[64];
    int t = threadIdx.x;  // 128 threads
    if (t < 64) pooled[t] = (float)(g_pool_sum[t] / (double)N);
    else        pooled[t] = __int_as_float(g_pool_max[t - 64]);
    __syncthreads();
    if (t < 64) {
        float acc = bc1[t];
        for (int i = 0; i < 128; i++) acc += pooled[i] * Wc1[i * 64 + t];
        z[t] = fmaxf(acc, 0.f);
    }
    __syncthreads();
    if (t < 2) {
        float acc = bc2[t];
        for (int j = 0; j < 64; j++) acc += z[j] * Wc2[j * 2 + t];
        out[t] = acc;
    }
}

// ---------------- launch ----------------
static inline int cdiv(long long a, long long b) { return (int)((a + b - 1) / b); }

extern "C" void kernel_launch(void* const* d_in, const int* in_sizes, int n_in,
                              void* d_out, int out_size) {
    const float* x     = (const float*)d_in[0];
    const void*  ei    = d_in[1];
    const float* W0    = (const float*)d_in[2];
    const float* b0    = (const float*)d_in[3];
    const float* asrc0 = (const float*)d_in[4];
    const float* adst0 = (const float*)d_in[5];
    const float* g0    = (const float*)d_in[6];
    const float* be0   = (const float*)d_in[7];
    const float* W1    = (const float*)d_in[8];
    const float* b1    = (const float*)d_in[9];
    const float* asrc1 = (const float*)d_in[10];
    const float* adst1 = (const float*)d_in[11];
    const float* g1    = (const float*)d_in[12];
    const float* be1   = (const float*)d_in[13];
    const float* W2    = (const float*)d_in[14];
    const float* b2    = (const float*)d_in[15];
    const float* asrc2 = (const float*)d_in[16];
    const float* adst2 = (const float*)d_in[17];
    const float* g2    = (const float*)d_in[18];
    const float* be2   = (const float*)d_in[19];
    const float* Wc1   = (const float*)d_in[20];
    const float* bc1   = (const float*)d_in[21];
    const float* Wc2   = (const float*)d_in[22];
    const float* bc2   = (const float*)d_in[23];

    int N  = in_sizes[0] / 128;   // 50000
    int E  = in_sizes[1] / 2;     // 800000
    int ET = E + N;               // with self-loops
    float invN = 1.0f / (float)N;

    float* pout = nullptr;
    cudaGetSymbolAddress((void**)&pout, g_out);

    detect_kernel<<<1, 32>>>(ei);

    // ---------------- layer 0: Fin=128, H=4, C=64 ----------------
    sgemm64<<<dim3(256 / 64, cdiv(N, 64)), 256>>>(x, W0, N, 128, 256);
    init_layer<<<2048, 256>>>(N * 256, N * 4);
    sd_kernel<4><<<cdiv((long long)N * 32, 256), 256>>>(asrc0, adst0, N);
    edge_max<4><<<cdiv(ET, 256), 256>>>(ei, E, ET);
    edge_den<4><<<cdiv(ET, 256), 256>>>(ei, E, ET);
    edge_agg<4><<<cdiv((long long)ET * 32, 256), 256>>>(ei, E, ET);
    bn_init<<<1, 256>>>();
    bn_stats<<<512, 256>>>(b0, 256, N);
    bn_final<<<1, 256>>>(g0, be0, 256, invN);
    bn_apply<<<2048, 256>>>(b0, 256, N * 256);

    // ---------------- layer 1: Fin=256, H=4, C=64 ----------------
    sgemm64<<<dim3(256 / 64, cdiv(N, 64)), 256>>>(pout, W1, N, 256, 256);
    init_layer<<<2048, 256>>>(N * 256, N * 4);
    sd_kernel<4><<<cdiv((long long)N * 32, 256), 256>>>(asrc1, adst1, N);
    edge_max<4><<<cdiv(ET, 256), 256>>>(ei, E, ET);
    edge_den<4><<<cdiv(ET, 256), 256>>>(ei, E, ET);
    edge_agg<4><<<cdiv((long long)ET * 32, 256), 256>>>(ei, E, ET);
    bn_init<<<1, 256>>>();
    bn_stats<<<512, 256>>>(b1, 256, N);
    bn_final<<<1, 256>>>(g1, be1, 256, invN);
    bn_apply<<<2048, 256>>>(b1, 256, N * 256);

    // ---------------- layer 2: Fin=256, H=1, C=64 ----------------
    sgemm64<<<dim3(64 / 64, cdiv(N, 64)), 256>>>(pout, W2, N, 256, 64);
    init_layer<<<2048, 256>>>(N * 64, N * 1);
    sd_kernel<1><<<cdiv((long long)N * 32, 256), 256>>>(asrc2, adst2, N);
    edge_max<1><<<cdiv(ET, 256), 256>>>(ei, E, ET);
    edge_den<1><<<cdiv(ET, 256), 256>>>(ei, E, ET);
    edge_agg<1><<<cdiv((long long)ET * 32, 256), 256>>>(ei, E, ET);
    bn_init<<<1, 256>>>();
    bn_stats<<<512, 256>>>(b2, 64, N);
    bn_final<<<1, 256>>>(g2, be2, 64, invN);
    bn_apply<<<2048, 256>>>(b2, 64, N * 64);

    // ---------------- pooling + classifier ----------------
    pool_init<<<1, 64>>>();
    pool_kernel<<<512, 256>>>(N);
    classifier<<<1, 128>>>(Wc1, bc1, Wc2, bc2, (float*)d_out, N);
}

// round 2
// speedup vs baseline: 1.4401x; 1.4401x over previous
#include <cuda_runtime.h>
#include <math.h>

// ---------------- problem constants (fixed-shape problem) ----------------
#define NMAX   50000
#define EMAX   800000
#define ETMAX  (EMAX + NMAX)
#define WD     256          // heads*Hd for layers 0/1
#define HDIM   64

// ---------------- scratch (no allocations allowed) ----------------
__device__ float  g_h  [(size_t)NMAX * WD];   // GEMM output  h = x @ W
__device__ float  g_out[(size_t)NMAX * WD];   // aggregated output (then bn'd in place)
__device__ float  g_s  [NMAX * 4];
__device__ float  g_d  [NMAX * 4];
__device__ double g_bnsum[WD];
__device__ double g_bnsq [WD];
__device__ float  g_scale[WD];
__device__ float  g_shift[WD];
__device__ double g_pool_sum[HDIM];
__device__ int    g_pool_max[HDIM];
__device__ int    g_is64;
// CSR (dst-major) of the edge list incl. self-loops; built once, reused by all layers
__device__ int    g_deg   [NMAX];
__device__ int    g_cursor[NMAX];
__device__ int    g_rowptr[NMAX + 1];
__device__ int    g_csr   [ETMAX];

// ---------------- helpers ----------------
__device__ __forceinline__ void get_edge(const void* ei, int e, int E, int& s, int& d) {
    if (e >= E) { s = d = e - E; return; }          // self-loops appended
    if (g_is64) {
        const long long* p = (const long long*)ei;
        s = (int)p[e]; d = (int)p[(size_t)E + e];
    } else {
        const int* p = (const int*)ei;
        s = p[e]; d = p[E + e];
    }
}

// detect int32 vs int64 edge_index on device (keeps launch graph static)
__global__ void detect_kernel(const void* ei) {
    if (threadIdx.x == 0 && blockIdx.x == 0) {
        const unsigned* w = (const unsigned*)ei;
        int is64 = 1;
        for (int i = 0; i < 8; i++)
            if (w[2 * i + 1] != 0u) is64 = 0;   // int64 values < 2^31 -> high words zero
        g_is64 = is64;
    }
}

// ---------------- CSR build ----------------
__global__ void csr_zero(int N) {
    int i = blockIdx.x * blockDim.x + threadIdx.x;
    if (i < N) { g_deg[i] = 0; g_cursor[i] = 0; }
}

__global__ void csr_hist(const void* __restrict__ ei, int E, int ET) {
    int e = blockIdx.x * blockDim.x + threadIdx.x;
    if (e >= ET) return;
    int s, d; get_edge(ei, e, E, s, d);
    atomicAdd(&g_deg[d], 1);
}

__global__ void csr_scan(int N) {
    __shared__ int part[1024];
    int t = threadIdx.x;
    int chunk = (N + 1023) / 1024;
    int start = t * chunk;
    int end   = start + chunk < N ? start + chunk : N;
    int s = 0;
    for (int i = start; i < end; i++) s += g_deg[i];
    part[t] = s;
    __syncthreads();
    for (int o = 1; o < 1024; o <<= 1) {
        int v = (t >= o) ? part[t - o] : 0;
        __syncthreads();
        part[t] += v;
        __syncthreads();
    }
    int base = (t == 0) ? 0 : part[t - 1];
    for (int i = start; i < end; i++) { g_rowptr[i] = base; base += g_deg[i]; }
    if (t == 1023) g_rowptr[N] = part[1023];
}

__global__ void csr_scatter(const void* __restrict__ ei, int E, int ET) {
    int e = blockIdx.x * blockDim.x + threadIdx.x;
    if (e >= ET) return;
    int s, d; get_edge(ei, e, E, s, d);
    int pos = g_rowptr[d] + atomicAdd(&g_cursor[d], 1);
    g_csr[pos] = s;
}

// ---------------- SGEMM: C(g_h) = A[MxK] @ B[KxNc], 64x64 tile, 4x4/thread ----------------
__global__ __launch_bounds__(256) void sgemm64(const float* __restrict__ A,
                                               const float* __restrict__ B,
                                               int M, int K, int Nc) {
    __shared__ float As[16][65];
    __shared__ float Bs[16][64];
    int tid  = threadIdx.x;
    int brow = blockIdx.y, bcol = blockIdx.x;
    int tr = tid >> 4;            // 0..15
    int tc = tid & 15;            // 0..15
    int a_row = tid >> 2;         // 0..63
    int a_col = (tid & 3) << 2;   // 0,4,8,12
    int b_row = tid >> 4;         // 0..15
    int b_col = (tid & 15) << 2;  // 0..60
    int grow = brow * 64;
    float acc[4][4] = {};

    for (int k0 = 0; k0 < K; k0 += 16) {
        float4 av = make_float4(0.f, 0.f, 0.f, 0.f);
        if (grow + a_row < M)
            av = *(const float4*)&A[(size_t)(grow + a_row) * K + k0 + a_col];
        float4 bv = *(const float4*)&B[(size_t)(k0 + b_row) * Nc + bcol * 64 + b_col];
        As[a_col + 0][a_row] = av.x;
        As[a_col + 1][a_row] = av.y;
        As[a_col + 2][a_row] = av.z;
        As[a_col + 3][a_row] = av.w;
        *(float4*)&Bs[b_row][b_col] = bv;
        __syncthreads();
#pragma unroll
        for (int kk = 0; kk < 16; kk++) {
            float a[4], b[4];
#pragma unroll
            for (int i = 0; i < 4; i++) a[i] = As[kk][tr * 4 + i];
#pragma unroll
            for (int j = 0; j < 4; j++) b[j] = Bs[kk][tc * 4 + j];
#pragma unroll
            for (int i = 0; i < 4; i++)
#pragma unroll
                for (int j = 0; j < 4; j++) acc[i][j] += a[i] * b[j];
        }
        __syncthreads();
    }
#pragma unroll
    for (int i = 0; i < 4; i++) {
        int r = grow + tr * 4 + i;
        if (r < M) {
            float4 v = make_float4(acc[i][0], acc[i][1], acc[i][2], acc[i][3]);
            *(float4*)&g_h[(size_t)r * Nc + bcol * 64 + tc * 4] = v;
        }
    }
}

// ---------------- s/d attention logits: warp per node ----------------
template <int H>
__global__ void sd_kernel(const float* __restrict__ asrc, const float* __restrict__ adst, int N) {
    const int T = H * 64;
    int warp = (blockIdx.x * blockDim.x + threadIdx.x) >> 5;
    int lane = threadIdx.x & 31;
    if (warp >= N) return;
    float as[H], ad[H];
#pragma unroll
    for (int h = 0; h < H; h++) { as[h] = 0.f; ad[h] = 0.f; }
    for (int idx = lane; idx < T; idx += 32) {
        float hv = g_h[(size_t)warp * T + idx];
        int hd = idx >> 6;
        as[hd] += hv * asrc[idx];
        ad[hd] += hv * adst[idx];
    }
#pragma unroll
    for (int h = 0; h < H; h++) {
        float a = as[h], d = ad[h];
        for (int o = 16; o; o >>= 1) {
            a += __shfl_xor_sync(0xffffffffu, a, o);
            d += __shfl_xor_sync(0xffffffffu, d, o);
        }
        if (lane == 0) { g_s[warp * H + h] = a; g_d[warp * H + h] = d; }
    }
}

// ---------------- fused segment softmax + aggregation: warp per destination ----------------
template <int H>
__global__ __launch_bounds__(256) void gat_agg(int N) {
    const int T  = H * 64;
    const int CH = T / 32;             // channels per lane: 8 (H=4) or 2 (H=1)
    int warp = (blockIdx.x * blockDim.x + threadIdx.x) >> 5;
    int lane = threadIdx.x & 31;
    if (warp >= N) return;
    int n = warp;

    float sdd[H];
#pragma unroll
    for (int h = 0; h < H; h++) sdd[h] = g_d[n * H + h];

    int r0 = g_rowptr[n], r1 = g_rowptr[n + 1];

    // pass 1: per-head max over incoming edges (lanes partition edges)
    float mx[H];
#pragma unroll
    for (int h = 0; h < H; h++) mx[h] = -1e30f;
    for (int i = r0 + lane; i < r1; i += 32) {
        int s = g_csr[i];
#pragma unroll
        for (int h = 0; h < H; h++) {
            float v = g_s[s * H + h] + sdd[h];
            v = v > 0.f ? v : 0.2f * v;
            mx[h] = fmaxf(mx[h], v);
        }
    }
#pragma unroll
    for (int h = 0; h < H; h++)
        for (int o = 16; o; o >>= 1)
            mx[h] = fmaxf(mx[h], __shfl_xor_sync(0xffffffffu, mx[h], o));

    // pass 2: per-head denom
    float den[H];
#pragma unroll
    for (int h = 0; h < H; h++) den[h] = 0.f;
    for (int i = r0 + lane; i < r1; i += 32) {
        int s = g_csr[i];
#pragma unroll
        for (int h = 0; h < H; h++) {
            float v = g_s[s * H + h] + sdd[h];
            v = v > 0.f ? v : 0.2f * v;
            den[h] += expf(v - mx[h]);
        }
    }
#pragma unroll
    for (int h = 0; h < H; h++) {
        for (int o = 16; o; o >>= 1)
            den[h] += __shfl_xor_sync(0xffffffffu, den[h], o);
        den[h] = 1.f / (den[h] + 1e-16f);     // invert once
    }

    // pass 3: weighted aggregation; whole warp cooperates per edge
    const int myh = (lane * CH) >> 6;          // head owning this lane's channels
    const float mymx  = mx[myh];
    const float myden = den[myh];
    const float mysdd = sdd[myh];
    float acc[CH];
#pragma unroll
    for (int c = 0; c < CH; c++) acc[c] = 0.f;

    for (int base = r0; base < r1; base += 32) {
        int srcs = (base + lane < r1) ? g_csr[base + lane] : 0;
        int cnt = r1 - base; if (cnt > 32) cnt = 32;
        for (int j = 0; j < cnt; j++) {
            int s = __shfl_sync(0xffffffffu, srcs, j);
            float v = g_s[s * H + myh] + mysdd;
            v = v > 0.f ? v : 0.2f * v;
            float alpha = expf(v - mymx) * myden;
            const float* hp = &g_h[(size_t)s * T + lane * CH];
            if (CH == 8) {
                float4 h0 = *(const float4*)hp;
                float4 h1 = *(const float4*)(hp + 4);
                acc[0] += h0.x * alpha; acc[1] += h0.y * alpha;
                acc[2] += h0.z * alpha; acc[3] += h0.w * alpha;
                acc[4] += h1.x * alpha; acc[5] += h1.y * alpha;
                acc[6] += h1.z * alpha; acc[7] += h1.w * alpha;
            } else {
                float2 h0 = *(const float2*)hp;
                acc[0] += h0.x * alpha; acc[1] += h0.y * alpha;
            }
        }
    }

    float* op = &g_out[(size_t)n * T + lane * CH];
    if (CH == 8) {
        *(float4*)op       = make_float4(acc[0], acc[1], acc[2], acc[3]);
        *(float4*)(op + 4) = make_float4(acc[4], acc[5], acc[6], acc[7]);
    } else {
        *(float2*)op = make_float2(acc[0], acc[1]);
    }
}

// ---------------- batchnorm ----------------
__global__ void bn_init() {
    int c = threadIdx.x;
    g_bnsum[c] = 0.0; g_bnsq[c] = 0.0;
}

__global__ void bn_stats(const float* __restrict__ bias, int C, int N) {
    int rpb = 256 / C;                 // rows touched per block iteration
    int c  = threadIdx.x % C;
    int r0 = blockIdx.x * rpb + threadIdx.x / C;
    double s = 0.0, q = 0.0;
    for (int r = r0; r < N; r += gridDim.x * rpb) {
        float v = g_out[(size_t)r * C + c] + bias[c];
        s += v; q += (double)v * v;
    }
    atomicAdd(&g_bnsum[c], s);
    atomicAdd(&g_bnsq[c], q);
}

__global__ void bn_final(const float* __restrict__ gamma, const float* __restrict__ beta,
                         int C, float inv_n) {
    int c = threadIdx.x;
    if (c >= C) return;
    float mu  = (float)(g_bnsum[c] * inv_n);
    float var = (float)(g_bnsq[c] * inv_n) - mu * mu;
    float sc  = gamma[c] * rsqrtf(var + 1e-5f);
    g_scale[c] = sc;
    g_shift[c] = beta[c] - sc * mu;
}

__global__ void bn_apply(const float* __restrict__ bias, int C, int total) {
    int stride = gridDim.x * blockDim.x;
    for (int i = blockIdx.x * blockDim.x + threadIdx.x; i < total; i += stride) {
        int c = i & (C - 1);
        float v = g_out[i] + bias[c];
        v = g_scale[c] * v + g_shift[c];
        g_out[i] = fmaxf(v, 0.f);
    }
}

// ---------------- global pooling over N ----------------
__global__ void pool_init() {
    int c = threadIdx.x;
    g_pool_sum[c] = 0.0;
    g_pool_max[c] = 0;          // values are post-ReLU (>= 0); bits(0.f)=0
}

__global__ void pool_kernel(int N) {
    __shared__ double ss[64];
    __shared__ int    sm[64];
    int t = threadIdx.x;
    if (t < 64) { ss[t] = 0.0; sm[t] = 0; }
    __syncthreads();
    int c  = t & 63;
    int r0 = blockIdx.x * 4 + (t >> 6);
    double ls = 0.0; float lm = 0.f;
    for (int r = r0; r < N; r += gridDim.x * 4) {
        float v = g_out[(size_t)r * 64 + c];
        ls += v; lm = fmaxf(lm, v);
    }
    atomicAdd(&ss[c], ls);
    atomicMax(&sm[c], __float_as_int(lm));
    __syncthreads();
    if (t < 64) {
        atomicAdd(&g_pool_sum[t], ss[t]);
        atomicMax(&g_pool_max[t], sm[t]);
    }
}

// ---------------- classifier head ----------------
__global__ void classifier(const float* __restrict__ Wc1, const float* __restrict__ bc1,
                           const float* __restrict__ Wc2, const float* __restrict__ bc2,
                           float* __restrict__ out, int N) {
    __shared__ float pooled[128];
    __shared__ float z[64];
    int t = threadIdx.x;  // 128 threads
    if (t < 64) pooled[t] = (float)(g_pool_sum[t] / (double)N);
    else        pooled[t] = __int_as_float(g_pool_max[t - 64]);
    __syncthreads();
    if (t < 64) {
        float acc = bc1[t];
        for (int i = 0; i < 128; i++) acc += pooled[i] * Wc1[i * 64 + t];
        z[t] = fmaxf(acc, 0.f);
    }
    __syncthreads();
    if (t < 2) {
        float acc = bc2[t];
        for (int j = 0; j < 64; j++) acc += z[j] * Wc2[j * 2 + t];
        out[t] = acc;
    }
}

// ---------------- launch ----------------
static inline int cdiv(long long a, long long b) { return (int)((a + b - 1) / b); }

extern "C" void kernel_launch(void* const* d_in, const int* in_sizes, int n_in,
                              void* d_out, int out_size) {
    const float* x     = (const float*)d_in[0];
    const void*  ei    = d_in[1];
    const float* W0    = (const float*)d_in[2];
    const float* b0    = (const float*)d_in[3];
    const float* asrc0 = (const float*)d_in[4];
    const float* adst0 = (const float*)d_in[5];
    const float* g0    = (const float*)d_in[6];
    const float* be0   = (const float*)d_in[7];
    const float* W1    = (const float*)d_in[8];
    const float* b1    = (const float*)d_in[9];
    const float* asrc1 = (const float*)d_in[10];
    const float* adst1 = (const float*)d_in[11];
    const float* g1    = (const float*)d_in[12];
    const float* be1   = (const float*)d_in[13];
    const float* W2    = (const float*)d_in[14];
    const float* b2    = (const float*)d_in[15];
    const float* asrc2 = (const float*)d_in[16];
    const float* adst2 = (const float*)d_in[17];
    const float* g2    = (const float*)d_in[18];
    const float* be2   = (const float*)d_in[19];
    const float* Wc1   = (const float*)d_in[20];
    const float* bc1   = (const float*)d_in[21];
    const float* Wc2   = (const float*)d_in[22];
    const float* bc2   = (const float*)d_in[23];

    int N  = in_sizes[0] / 128;   // 50000
    int E  = in_sizes[1] / 2;     // 800000
    int ET = E + N;               // with self-loops
    float invN = 1.0f / (float)N;

    float* pout = nullptr;
    cudaGetSymbolAddress((void**)&pout, g_out);

    detect_kernel<<<1, 32>>>(ei);

    // ---------------- build dst-major CSR once (reused by all 3 layers) ----------------
    csr_zero<<<cdiv(N, 256), 256>>>(N);
    csr_hist<<<cdiv(ET, 256), 256>>>(ei, E, ET);
    csr_scan<<<1, 1024>>>(N);
    csr_scatter<<<cdiv(ET, 256), 256>>>(ei, E, ET);

    // ---------------- layer 0: Fin=128, H=4, C=64 ----------------
    sgemm64<<<dim3(256 / 64, cdiv(N, 64)), 256>>>(x, W0, N, 128, 256);
    sd_kernel<4><<<cdiv((long long)N * 32, 256), 256>>>(asrc0, adst0, N);
    gat_agg<4><<<cdiv((long long)N * 32, 256), 256>>>(N);
    bn_init<<<1, 256>>>();
    bn_stats<<<512, 256>>>(b0, 256, N);
    bn_final<<<1, 256>>>(g0, be0, 256, invN);
    bn_apply<<<2048, 256>>>(b0, 256, N * 256);

    // ---------------- layer 1: Fin=256, H=4, C=64 ----------------
    sgemm64<<<dim3(256 / 64, cdiv(N, 64)), 256>>>(pout, W1, N, 256, 256);
    sd_kernel<4><<<cdiv((long long)N * 32, 256), 256>>>(asrc1, adst1, N);
    gat_agg<4><<<cdiv((long long)N * 32, 256), 256>>>(N);
    bn_init<<<1, 256>>>();
    bn_stats<<<512, 256>>>(b1, 256, N);
    bn_final<<<1, 256>>>(g1, be1, 256, invN);
    bn_apply<<<2048, 256>>>(b1, 256, N * 256);

    // ---------------- layer 2: Fin=256, H=1, C=64 ----------------
    sgemm64<<<dim3(64 / 64, cdiv(N, 64)), 256>>>(pout, W2, N, 256, 64);
    sd_kernel<1><<<cdiv((long long)N * 32, 256), 256>>>(asrc2, adst2, N);
    gat_agg<1><<<cdiv((long long)N * 32, 256), 256>>>(N);
    bn_init<<<1, 256>>>();
    bn_stats<<<512, 256>>>(b2, 64, N);
    bn_final<<<1, 256>>>(g2, be2, 64, invN);
    bn_apply<<<2048, 256>>>(b2, 64, N * 64);

    // ---------------- pooling + classifier ----------------
    pool_init<<<1, 64>>>();
    pool_kernel<<<512, 256>>>(N);
    classifier<<<1, 128>>>(Wc1, bc1, Wc2, bc2, (float*)d_out, N);
}

// round 4
// speedup vs baseline: 1.7828x; 1.2379x over previous
#include <cuda_runtime.h>
#include <cuda_bf16.h>
#include <math.h>
#include <stdint.h>

// ---------------- problem constants (fixed-shape problem) ----------------
#define NMAX   50000
#define EMAX   800000
#define ETMAX  (EMAX + NMAX)
#define WD     256
#define HDIM   64

// ---------------- scratch (no allocations allowed) ----------------
__device__ float  g_h  [(size_t)NMAX * WD];
__device__ float  g_out[(size_t)NMAX * WD];
__device__ float  g_s  [NMAX * 4];
__device__ float  g_d  [NMAX * 4];
__device__ double g_bnsum[WD];
__device__ double g_bnsq [WD];
__device__ float  g_scale[WD];
__device__ float  g_shift[WD];
__device__ double g_pool_sum[HDIM];
__device__ int    g_pool_max[HDIM];
__device__ int    g_is64;
__device__ int    g_deg   [NMAX];
__device__ int    g_cursor[NMAX];
__device__ int    g_rowptr[NMAX + 1];
__device__ int    g_csr   [ETMAX];
__device__ int    g_bsum[256];
__device__ int    g_boff[256];
// bf16 split operands for tensor-core GEMM
__device__ __nv_bfloat16 g_Ah[(size_t)NMAX * WD];
__device__ __nv_bfloat16 g_Al[(size_t)NMAX * WD];
__device__ __nv_bfloat16 g_Bh[WD * WD];
__device__ __nv_bfloat16 g_Bl[WD * WD];

// ---------------- edge helpers ----------------
__device__ __forceinline__ void get_edge(const void* ei, int e, int E, int& s, int& d) {
    if (e >= E) { s = d = e - E; return; }
    if (g_is64) {
        const long long* p = (const long long*)ei;
        s = (int)p[e]; d = (int)p[(size_t)E + e];
    } else {
        const int* p = (const int*)ei;
        s = p[e]; d = p[E + e];
    }
}

__global__ void detect_kernel(const void* ei) {
    if (threadIdx.x == 0 && blockIdx.x == 0) {
        const unsigned* w = (const unsigned*)ei;
        int is64 = 1;
        for (int i = 0; i < 8; i++)
            if (w[2 * i + 1] != 0u) is64 = 0;
        g_is64 = is64;
    }
}

// ---------------- CSR build ----------------
__global__ void csr_zero(int N) {
    int i = blockIdx.x * blockDim.x + threadIdx.x;
    if (i < N) { g_deg[i] = 0; g_cursor[i] = 0; }
}
__global__ void csr_hist(const void* __restrict__ ei, int E, int ET) {
    int e = blockIdx.x * blockDim.x + threadIdx.x;
    if (e >= ET) return;
    int s, d; get_edge(ei, e, E, s, d);
    atomicAdd(&g_deg[d], 1);
}
__global__ void scan1(int N) {
    __shared__ int sh[256];
    int i = blockIdx.x * 256 + threadIdx.x;
    int v = (i < N) ? g_deg[i] : 0;
    sh[threadIdx.x] = v;
    __syncthreads();
    for (int o = 128; o; o >>= 1) {
        if (threadIdx.x < o) sh[threadIdx.x] += sh[threadIdx.x + o];
        __syncthreads();
    }
    if (threadIdx.x == 0) g_bsum[blockIdx.x] = sh[0];
}
__global__ void scan2(int nb) {
    __shared__ int sh[256];
    int t = threadIdx.x;
    int v = (t < nb) ? g_bsum[t] : 0;
    sh[t] = v;
    __syncthreads();
    for (int o = 1; o < 256; o <<= 1) {
        int u = (t >= o) ? sh[t - o] : 0;
        __syncthreads();
        sh[t] += u;
        __syncthreads();
    }
    g_boff[t] = sh[t] - v;     // exclusive
}
__global__ void scan3(int N, int ET) {
    __shared__ int sh[256];
    int t = threadIdx.x;
    int i = blockIdx.x * 256 + t;
    int v = (i < N) ? g_deg[i] : 0;
    sh[t] = v;
    __syncthreads();
    for (int o = 1; o < 256; o <<= 1) {
        int u = (t >= o) ? sh[t - o] : 0;
        __syncthreads();
        sh[t] += u;
        __syncthreads();
    }
    if (i < N) g_rowptr[i] = g_boff[blockIdx.x] + sh[t] - v;
    if (blockIdx.x == 0 && t == 0) g_rowptr[N] = ET;
}
__global__ void csr_scatter(const void* __restrict__ ei, int E, int ET) {
    int e = blockIdx.x * blockDim.x + threadIdx.x;
    if (e >= ET) return;
    int s, d; get_edge(ei, e, E, s, d);
    int pos = g_rowptr[d] + atomicAdd(&g_cursor[d], 1);
    g_csr[pos] = s;
}

// ---------------- fp32 -> bf16 hi/lo splits ----------------
__global__ void conv_split(const float* __restrict__ src, __nv_bfloat16* __restrict__ hi,
                           __nv_bfloat16* __restrict__ lo, size_t n) {
    size_t stride = (size_t)gridDim.x * blockDim.x;
    for (size_t i = (size_t)blockIdx.x * blockDim.x + threadIdx.x; i < n; i += stride) {
        float x = src[i];
        __nv_bfloat16 h = __float2bfloat16(x);
        hi[i] = h;
        lo[i] = __float2bfloat16(x - __bfloat162float(h));
    }
}
// W[K x NC] (row-major) -> Bh/Bl[NC x K] (transposed, row-major)
__global__ void conv_w(const float* __restrict__ W, __nv_bfloat16* __restrict__ hi,
                       __nv_bfloat16* __restrict__ lo, int K, int NC) {
    int i = blockIdx.x * blockDim.x + threadIdx.x;
    if (i >= K * NC) return;
    int k = i / NC, n = i % NC;
    float x = W[i];
    __nv_bfloat16 h = __float2bfloat16(x);
    hi[(size_t)n * K + k] = h;
    lo[(size_t)n * K + k] = __float2bfloat16(x - __bfloat162float(h));
}

// ---------------- mma.sync helpers ----------------
__device__ __forceinline__ void ldsm_x4(uint32_t* r, uint32_t addr) {
    asm volatile("ldmatrix.sync.aligned.m8n8.x4.shared.b16 {%0,%1,%2,%3}, [%4];"
                 : "=r"(r[0]), "=r"(r[1]), "=r"(r[2]), "=r"(r[3]) : "r"(addr));
}
__device__ __forceinline__ void mma_bf16(float* c, const uint32_t* a, const uint32_t* b) {
    asm volatile("mma.sync.aligned.m16n8k16.row.col.f32.bf16.bf16.f32 "
                 "{%0,%1,%2,%3}, {%4,%5,%6,%7}, {%8,%9}, {%0,%1,%2,%3};"
                 : "+f"(c[0]), "+f"(c[1]), "+f"(c[2]), "+f"(c[3])
                 : "r"(a[0]), "r"(a[1]), "r"(a[2]), "r"(a[3]), "r"(b[0]), "r"(b[1]));
}

// ---------------- HMMA GEMM: C[M x NC] = A @ W  (A = Ah+Al, B = Bh+Bl, drop Al*Bl) ----
// Block tile 128 x BN, 8 warps. B stored [NC x K] (col-major K x NC).
template <int BN>
__global__ __launch_bounds__(256)
void hmma_gemm(const __nv_bfloat16* __restrict__ Ah, const __nv_bfloat16* __restrict__ Al,
               const __nv_bfloat16* __restrict__ Bh, const __nv_bfloat16* __restrict__ Bl,
               float* __restrict__ Cout, int M, int K, int NC) {
    constexpr int WN = BN / 32;          // warps along N (4 or 2)
    constexpr int WM = 8 / WN;           // warps along M (2 or 4)
    constexpr int WTM = 128 / WM;        // warp tile M (64 or 32)
    constexpr int MF = WTM / 16;         // m-frags per warp (4 or 2)
    constexpr int AST = 40;              // smem row stride in bf16 (80B: conflict-free ldmatrix)

    __shared__ __nv_bfloat16 sAh[128][AST];
    __shared__ __nv_bfloat16 sAl[128][AST];
    __shared__ __nv_bfloat16 sBh[BN][AST];
    __shared__ __nv_bfloat16 sBl[BN][AST];

    const int tid  = threadIdx.x;
    const int wid  = tid >> 5, lane = tid & 31;
    const int row0 = blockIdx.y * 128;
    const int bn0  = blockIdx.x * BN;
    const int warpM = wid % WM, warpN = wid / WM;
    const int m0 = warpM * WTM;
    const int n0 = warpN * 32;

    float acc[MF][4][4];
#pragma unroll
    for (int i = 0; i < MF; i++)
#pragma unroll
        for (int j = 0; j < 4; j++)
#pragma unroll
            for (int k = 0; k < 4; k++) acc[i][j][k] = 0.f;

    for (int k0 = 0; k0 < K; k0 += 32) {
        // load A tiles (128 x 32 bf16, 16B chunks)
#pragma unroll
        for (int it = 0; it < 2; it++) {
            int i = tid + it * 256;            // 0..511
            int r = i >> 2, seg = i & 3;
            uint4 vh = make_uint4(0, 0, 0, 0), vl = make_uint4(0, 0, 0, 0);
            if (row0 + r < M) {
                size_t off = (size_t)(row0 + r) * K + k0 + seg * 8;
                vh = *(const uint4*)(Ah + off);
                vl = *(const uint4*)(Al + off);
            }
            *(uint4*)&sAh[r][seg * 8] = vh;
            *(uint4*)&sAl[r][seg * 8] = vl;
        }
        // load B tiles (BN x 32 bf16)
#pragma unroll
        for (int it = 0; it < BN / 64; it++) {
            int i = tid + it * 256;
            int r = i >> 2, seg = i & 3;
            size_t off = (size_t)(bn0 + r) * K + k0 + seg * 8;
            *(uint4*)&sBh[r][seg * 8] = *(const uint4*)(Bh + off);
            *(uint4*)&sBl[r][seg * 8] = *(const uint4*)(Bl + off);
        }
        __syncthreads();

#pragma unroll
        for (int ks = 0; ks < 2; ks++) {
            const int kc = ks * 16;
            uint32_t afh[MF][4], afl[MF][4], bfh[2][4], bfl[2][4];
            // A fragments: lane -> row (l&15), k-offset ((l>>4)*8)
            int ar = (lane & 15), ak = kc + ((lane >> 4) << 3);
#pragma unroll
            for (int fi = 0; fi < MF; fi++) {
                uint32_t ad = (uint32_t)__cvta_generic_to_shared(&sAh[m0 + fi * 16 + ar][ak]);
                ldsm_x4(afh[fi], ad);
                uint32_t ad2 = (uint32_t)__cvta_generic_to_shared(&sAl[m0 + fi * 16 + ar][ak]);
                ldsm_x4(afl[fi], ad2);
            }
            // B fragments: lane -> n (l&7)+((l>>4)*8), k-offset (l&8)
            int br = (lane & 7) + ((lane >> 4) << 3), bk = kc + (lane & 8);
#pragma unroll
            for (int g = 0; g < 2; g++) {
                uint32_t bd = (uint32_t)__cvta_generic_to_shared(&sBh[n0 + g * 16 + br][bk]);
                ldsm_x4(bfh[g], bd);
                uint32_t bd2 = (uint32_t)__cvta_generic_to_shared(&sBl[n0 + g * 16 + br][bk]);
                ldsm_x4(bfl[g], bd2);
            }
#pragma unroll
            for (int fi = 0; fi < MF; fi++)
#pragma unroll
                for (int ni = 0; ni < 4; ni++) {
                    mma_bf16(acc[fi][ni], afh[fi], &bfh[ni >> 1][(ni & 1) * 2]);
                    mma_bf16(acc[fi][ni], afh[fi], &bfl[ni >> 1][(ni & 1) * 2]);
                    mma_bf16(acc[fi][ni], afl[fi], &bfh[ni >> 1][(ni & 1) * 2]);
                }
        }
        __syncthreads();
    }

    // epilogue: C frag m16n8: c0,c1 @ (row t/4, col (t%4)*2), c2,c3 @ row+8
    const int crow = lane >> 2, ccol = (lane & 3) * 2;
#pragma unroll
    for (int fi = 0; fi < MF; fi++) {
        int r_lo = row0 + m0 + fi * 16 + crow;
        int r_hi = r_lo + 8;
#pragma unroll
        for (int ni = 0; ni < 4; ni++) {
            int c = bn0 + n0 + ni * 8 + ccol;
            if (r_lo < M)
                *(float2*)&Cout[(size_t)r_lo * NC + c] = make_float2(acc[fi][ni][0], acc[fi][ni][1]);
            if (r_hi < M)
                *(float2*)&Cout[(size_t)r_hi * NC + c] = make_float2(acc[fi][ni][2], acc[fi][ni][3]);
        }
    }
}

// ---------------- s/d attention logits: warp per node ----------------
template <int H>
__global__ void sd_kernel(const float* __restrict__ asrc, const float* __restrict__ adst, int N) {
    const int T = H * 64;
    int warp = (blockIdx.x * blockDim.x + threadIdx.x) >> 5;
    int lane = threadIdx.x & 31;
    if (warp >= N) return;
    float as[H], ad[H];
#pragma unroll
    for (int h = 0; h < H; h++) { as[h] = 0.f; ad[h] = 0.f; }
    for (int idx = lane; idx < T; idx += 32) {
        float hv = g_h[(size_t)warp * T + idx];
        int hd = idx >> 6;
        as[hd] += hv * asrc[idx];
        ad[hd] += hv * adst[idx];
    }
#pragma unroll
    for (int h = 0; h < H; h++) {
        float a = as[h], d = ad[h];
        for (int o = 16; o; o >>= 1) {
            a += __shfl_xor_sync(0xffffffffu, a, o);
            d += __shfl_xor_sync(0xffffffffu, d, o);
        }
        if (lane == 0) { g_s[warp * H + h] = a; g_d[warp * H + h] = d; }
    }
}

// ---------------- fused segment softmax + aggregation: warp per destination ----------------
template <int H>
__global__ __launch_bounds__(256) void gat_agg(int N) {
    const int T  = H * 64;
    const int CH = T / 32;
    int warp = (blockIdx.x * blockDim.x + threadIdx.x) >> 5;
    int lane = threadIdx.x & 31;
    if (warp >= N) return;
    int n = warp;

    float sdd[H];
#pragma unroll
    for (int h = 0; h < H; h++) sdd[h] = g_d[n * H + h];

    int r0 = g_rowptr[n], r1 = g_rowptr[n + 1];

    float mx[H];
#pragma unroll
    for (int h = 0; h < H; h++) mx[h] = -1e30f;
    for (int i = r0 + lane; i < r1; i += 32) {
        int s = g_csr[i];
#pragma unroll
        for (int h = 0; h < H; h++) {
            float v = g_s[s * H + h] + sdd[h];
            v = v > 0.f ? v : 0.2f * v;
            mx[h] = fmaxf(mx[h], v);
        }
    }
#pragma unroll
    for (int h = 0; h < H; h++)
        for (int o = 16; o; o >>= 1)
            mx[h] = fmaxf(mx[h], __shfl_xor_sync(0xffffffffu, mx[h], o));

    float den[H];
#pragma unroll
    for (int h = 0; h < H; h++) den[h] = 0.f;
    for (int i = r0 + lane; i < r1; i += 32) {
        int s = g_csr[i];
#pragma unroll
        for (int h = 0; h < H; h++) {
            float v = g_s[s * H + h] + sdd[h];
            v = v > 0.f ? v : 0.2f * v;
            den[h] += expf(v - mx[h]);
        }
    }
#pragma unroll
    for (int h = 0; h < H; h++) {
        for (int o = 16; o; o >>= 1)
            den[h] += __shfl_xor_sync(0xffffffffu, den[h], o);
        den[h] = 1.f / (den[h] + 1e-16f);
    }

    const int myh = (lane * CH) >> 6;
    const float mymx  = mx[myh];
    const float myden = den[myh];
    const float mysdd = sdd[myh];
    float acc[CH];
#pragma unroll
    for (int c = 0; c < CH; c++) acc[c] = 0.f;

    for (int base = r0; base < r1; base += 32) {
        int srcs = (base + lane < r1) ? g_csr[base + lane] : 0;
        int cnt = r1 - base; if (cnt > 32) cnt = 32;
        for (int j = 0; j < cnt; j++) {
            int s = __shfl_sync(0xffffffffu, srcs, j);
            float v = g_s[s * H + myh] + mysdd;
            v = v > 0.f ? v : 0.2f * v;
            float alpha = expf(v - mymx) * myden;
            const float* hp = &g_h[(size_t)s * T + lane * CH];
            if (CH == 8) {
                float4 h0 = *(const float4*)hp;
                float4 h1 = *(const float4*)(hp + 4);
                acc[0] += h0.x * alpha; acc[1] += h0.y * alpha;
                acc[2] += h0.z * alpha; acc[3] += h0.w * alpha;
                acc[4] += h1.x * alpha; acc[5] += h1.y * alpha;
                acc[6] += h1.z * alpha; acc[7] += h1.w * alpha;
            } else {
                float2 h0 = *(const float2*)hp;
                acc[0] += h0.x * alpha; acc[1] += h0.y * alpha;
            }
        }
    }

    float* op = &g_out[(size_t)n * T + lane * CH];
    if (CH == 8) {
        *(float4*)op       = make_float4(acc[0], acc[1], acc[2], acc[3]);
        *(float4*)(op + 4) = make_float4(acc[4], acc[5], acc[6], acc[7]);
    } else {
        *(float2*)op = make_float2(acc[0], acc[1]);
    }
}

// ---------------- batchnorm ----------------
__global__ void bn_init() {
    int c = threadIdx.x;
    g_bnsum[c] = 0.0; g_bnsq[c] = 0.0;
}
__global__ void bn_stats(const float* __restrict__ bias, int C, int N) {
    int rpb = 256 / C;
    int c  = threadIdx.x % C;
    int r0 = blockIdx.x * rpb + threadIdx.x / C;
    double s = 0.0, q = 0.0;
    for (int r = r0; r < N; r += gridDim.x * rpb) {
        float v = g_out[(size_t)r * C + c] + bias[c];
        s += v; q += (double)v * v;
    }
    atomicAdd(&g_bnsum[c], s);
    atomicAdd(&g_bnsq[c], q);
}
__global__ void bn_final(const float* __restrict__ gamma, const float* __restrict__ beta,
                         int C, float inv_n) {
    int c = threadIdx.x;
    if (c >= C) return;
    float mu  = (float)(g_bnsum[c] * inv_n);
    float var = (float)(g_bnsq[c] * inv_n) - mu * mu;
    float sc  = gamma[c] * rsqrtf(var + 1e-5f);
    g_scale[c] = sc;
    g_shift[c] = beta[c] - sc * mu;
}
__global__ void bn_apply(const float* __restrict__ bias, int C, int total) {
    int stride = gridDim.x * blockDim.x;
    for (int i = blockIdx.x * blockDim.x + threadIdx.x; i < total; i += stride) {
        int c = i & (C - 1);
        float v = g_out[i] + bias[c];
        v = g_scale[c] * v + g_shift[c];
        g_out[i] = fmaxf(v, 0.f);
    }
}

// ---------------- global pooling over N ----------------
__global__ void pool_init() {
    int c = threadIdx.x;
    g_pool_sum[c] = 0.0;
    g_pool_max[c] = 0;
}
__global__ void pool_kernel(int N) {
    __shared__ double ss[64];
    __shared__ int    sm[64];
    int t = threadIdx.x;
    if (t < 64) { ss[t] = 0.0; sm[t] = 0; }
    __syncthreads();
    int c  = t & 63;
    int r0 = blockIdx.x * 4 + (t >> 6);
    double ls = 0.0; float lm = 0.f;
    for (int r = r0; r < N; r += gridDim.x * 4) {
        float v = g_out[(size_t)r * 64 + c];
        ls += v; lm = fmaxf(lm, v);
    }
    atomicAdd(&ss[c], ls);
    atomicMax(&sm[c], __float_as_int(lm));
    __syncthreads();
    if (t < 64) {
        atomicAdd(&g_pool_sum[t], ss[t]);
        atomicMax(&g_pool_max[t], sm[t]);
    }
}

// ---------------- classifier head ----------------
__global__ void classifier(const float* __restrict__ Wc1, const float* __restrict__ bc1,
                           const float* __restrict__ Wc2, const float* __restrict__ bc2,
                           float* __restrict__ out, int N) {
    __shared__ float pooled[128];
    __shared__ float z[64];
    int t = threadIdx.x;
    if (t < 64) pooled[t] = (float)(g_pool_sum[t] / (double)N);
    else        pooled[t] = __int_as_float(g_pool_max[t - 64]);
    __syncthreads();
    if (t < 64) {
        float acc = bc1[t];
        for (int i = 0; i < 128; i++) acc += pooled[i] * Wc1[i * 64 + t];
        z[t] = fmaxf(acc, 0.f);
    }
    __syncthreads();
    if (t < 2) {
        float acc = bc2[t];
        for (int j = 0; j < 64; j++) acc += z[j] * Wc2[j * 2 + t];
        out[t] = acc;
    }
}

// ---------------- launch ----------------
static inline int cdiv(long long a, long long b) { return (int)((a + b - 1) / b); }

extern "C" void kernel_launch(void* const* d_in, const int* in_sizes, int n_in,
                              void* d_out, int out_size) {
    const float* x     = (const float*)d_in[0];
    const void*  ei    = d_in[1];
    const float* W0    = (const float*)d_in[2];
    const float* b0    = (const float*)d_in[3];
    const float* asrc0 = (const float*)d_in[4];
    const float* adst0 = (const float*)d_in[5];
    const float* g0    = (const float*)d_in[6];
    const float* be0   = (const float*)d_in[7];
    const float* W1    = (const float*)d_in[8];
    const float* b1    = (const float*)d_in[9];
    const float* asrc1 = (const float*)d_in[10];
    const float* adst1 = (const float*)d_in[11];
    const float* g1    = (const float*)d_in[12];
    const float* be1   = (const float*)d_in[13];
    const float* W2    = (const float*)d_in[14];
    const float* b2    = (const float*)d_in[15];
    const float* asrc2 = (const float*)d_in[16];
    const float* adst2 = (const float*)d_in[17];
    const float* g2    = (const float*)d_in[18];
    const float* be2   = (const float*)d_in[19];
    const float* Wc1   = (const float*)d_in[20];
    const float* bc1   = (const float*)d_in[21];
    const float* Wc2   = (const float*)d_in[22];
    const float* bc2   = (const float*)d_in[23];

    int N  = in_sizes[0] / 128;
    int E  = in_sizes[1] / 2;
    int ET = E + N;
    float invN = 1.0f / (float)N;

    float* pout = nullptr;
    float* ph   = nullptr;
    __nv_bfloat16 *pAh = nullptr, *pAl = nullptr, *pBh = nullptr, *pBl = nullptr;
    cudaGetSymbolAddress((void**)&pout, g_out);
    cudaGetSymbolAddress((void**)&ph,   g_h);
    cudaGetSymbolAddress((void**)&pAh,  g_Ah);
    cudaGetSymbolAddress((void**)&pAl,  g_Al);
    cudaGetSymbolAddress((void**)&pBh,  g_Bh);
    cudaGetSymbolAddress((void**)&pBl,  g_Bl);

    int gtiles = cdiv(N, 128);
    int nb = cdiv(N, 256);

    detect_kernel<<<1, 32>>>(ei);

    // ---------------- build dst-major CSR once ----------------
    csr_zero<<<cdiv(N, 256), 256>>>(N);
    csr_hist<<<cdiv(ET, 256), 256>>>(ei, E, ET);
    scan1<<<nb, 256>>>(N);
    scan2<<<1, 256>>>(nb);
    scan3<<<nb, 256>>>(N, ET);
    csr_scatter<<<cdiv(ET, 256), 256>>>(ei, E, ET);

    // ---------------- layer 0: Fin=128, H=4, C=64 ----------------
    conv_split<<<2048, 256>>>(x, pAh, pAl, (size_t)N * 128);
    conv_w<<<cdiv(128 * 256, 256), 256>>>(W0, pBh, pBl, 128, 256);
    hmma_gemm<128><<<dim3(2, gtiles), 256>>>(pAh, pAl, pBh, pBl, ph, N, 128, 256);
    sd_kernel<4><<<cdiv((long long)N * 32, 256), 256>>>(asrc0, adst0, N);
    gat_agg<4><<<cdiv((long long)N * 32, 256), 256>>>(N);
    bn_init<<<1, 256>>>();
    bn_stats<<<512, 256>>>(b0, 256, N);
    bn_final<<<1, 256>>>(g0, be0, 256, invN);
    bn_apply<<<2048, 256>>>(b0, 256, N * 256);

    // ---------------- layer 1: Fin=256, H=4, C=64 ----------------
    conv_split<<<2048, 256>>>(pout, pAh, pAl, (size_t)N * 256);
    conv_w<<<cdiv(256 * 256, 256), 256>>>(W1, pBh, pBl, 256, 256);
    hmma_gemm<128><<<dim3(2, gtiles), 256>>>(pAh, pAl, pBh, pBl, ph, N, 256, 256);
    sd_kernel<4><<<cdiv((long long)N * 32, 256), 256>>>(asrc1, adst1, N);
    gat_agg<4><<<cdiv((long long)N * 32, 256), 256>>>(N);
    bn_init<<<1, 256>>>();
    bn_stats<<<512, 256>>>(b1, 256, N);
    bn_final<<<1, 256>>>(g1, be1, 256, invN);
    bn_apply<<<2048, 256>>>(b1, 256, N * 256);

    // ---------------- layer 2: Fin=256, H=1, C=64 ----------------
    conv_split<<<2048, 256>>>(pout, pAh, pAl, (size_t)N * 256);
    conv_w<<<cdiv(256 * 64, 256), 256>>>(W2, pBh, pBl, 256, 64);
    hmma_gemm<64><<<dim3(1, gtiles), 256>>>(pAh, pAl, pBh, pBl, ph, N, 256, 64);
    sd_kernel<1><<<cdiv((long long)N * 32, 256), 256>>>(asrc2, adst2, N);
    gat_agg<1><<<cdiv((long long)N * 32, 256), 256>>>(N);
    bn_init<<<1, 256>>>();
    bn_stats<<<512, 256>>>(b2, 64, N);
    bn_final<<<1, 256>>>(g2, be2, 64, invN);
    bn_apply<<<2048, 256>>>(b2, 64, N * 64);

    // ---------------- pooling + classifier ----------------
    pool_init<<<1, 64>>>();
    pool_kernel<<<512, 256>>>(N);
    classifier<<<1, 128>>>(Wc1, bc1, Wc2, bc2, (float*)d_out, N);
}

// round 7
// speedup vs baseline: 1.8356x; 1.0297x over previous
#include <cuda_runtime.h>
#include <cuda_bf16.h>
#include <math.h>
#include <stdint.h>

// ---------------- problem constants ----------------
#define NMAX   50000
#define EMAX   800000
#define ETMAX  (EMAX + NMAX)
#define WD     256
#define HDIM   64

// ---------------- scratch ----------------
__device__ float  g_h  [(size_t)NMAX * WD];
__device__ float  g_out[(size_t)NMAX * WD];
__device__ float  g_s  [NMAX * 4];
__device__ float  g_d  [NMAX * 4];
__device__ double g_bnsum[WD];
__device__ double g_bnsq [WD];
__device__ float  g_scale[WD];
__device__ float  g_shift[WD];
__device__ double g_pool_sum[HDIM];
__device__ int    g_pool_max[HDIM];
__device__ int    g_is64;
__device__ int    g_deg   [NMAX];
__device__ int    g_cursor[NMAX];
__device__ int    g_rowptr[NMAX + 1];
__device__ int    g_csr   [ETMAX];
__device__ int    g_bsum[256];
__device__ int    g_boff[256];
__device__ __nv_bfloat16 g_Ah[(size_t)NMAX * WD];
__device__ __nv_bfloat16 g_Al[(size_t)NMAX * WD];
__device__ __nv_bfloat16 g_Bh[WD * WD];
__device__ __nv_bfloat16 g_Bl[WD * WD];

// ---------------- edge helpers ----------------
__device__ __forceinline__ void get_edge(const void* ei, int e, int E, int& s, int& d) {
    if (e >= E) { s = d = e - E; return; }
    if (g_is64) {
        const long long* p = (const long long*)ei;
        s = (int)p[e]; d = (int)p[(size_t)E + e];
    } else {
        const int* p = (const int*)ei;
        s = p[e]; d = p[E + e];
    }
}

__global__ void detect_kernel(const void* ei) {
    if (threadIdx.x == 0 && blockIdx.x == 0) {
        const unsigned* w = (const unsigned*)ei;
        int is64 = 1;
        for (int i = 0; i < 8; i++)
            if (w[2 * i + 1] != 0u) is64 = 0;
        g_is64 = is64;
    }
}

// ---------------- CSR build ----------------
__global__ void csr_zero(int N) {
    int i = blockIdx.x * blockDim.x + threadIdx.x;
    if (i < N) { g_deg[i] = 0; g_cursor[i] = 0; }
}
__global__ void csr_hist(const void* __restrict__ ei, int E, int ET) {
    int e = blockIdx.x * blockDim.x + threadIdx.x;
    if (e >= ET) return;
    int s, d; get_edge(ei, e, E, s, d);
    atomicAdd(&g_deg[d], 1);
}
__global__ void scan1(int N) {
    __shared__ int sh[256];
    int i = blockIdx.x * 256 + threadIdx.x;
    int v = (i < N) ? g_deg[i] : 0;
    sh[threadIdx.x] = v;
    __syncthreads();
    for (int o = 128; o; o >>= 1) {
        if (threadIdx.x < o) sh[threadIdx.x] += sh[threadIdx.x + o];
        __syncthreads();
    }
    if (threadIdx.x == 0) g_bsum[blockIdx.x] = sh[0];
}
__global__ void scan2(int nb) {
    __shared__ int sh[256];
    int t = threadIdx.x;
    int v = (t < nb) ? g_bsum[t] : 0;
    sh[t] = v;
    __syncthreads();
    for (int o = 1; o < 256; o <<= 1) {
        int u = (t >= o) ? sh[t - o] : 0;
        __syncthreads();
        sh[t] += u;
        __syncthreads();
    }
    g_boff[t] = sh[t] - v;
}
__global__ void scan3(int N, int ET) {
    __shared__ int sh[256];
    int t = threadIdx.x;
    int i = blockIdx.x * 256 + t;
    int v = (i < N) ? g_deg[i] : 0;
    sh[t] = v;
    __syncthreads();
    for (int o = 1; o < 256; o <<= 1) {
        int u = (t >= o) ? sh[t - o] : 0;
        __syncthreads();
        sh[t] += u;
        __syncthreads();
    }
    if (i < N) g_rowptr[i] = g_boff[blockIdx.x] + sh[t] - v;
    if (blockIdx.x == 0 && t == 0) g_rowptr[N] = ET;
}
__global__ void csr_scatter(const void* __restrict__ ei, int E, int ET) {
    int e = blockIdx.x * blockDim.x + threadIdx.x;
    if (e >= ET) return;
    int s, d; get_edge(ei, e, E, s, d);
    int pos = g_rowptr[d] + atomicAdd(&g_cursor[d], 1);
    g_csr[pos] = s;
}

// ---------------- fp32 -> bf16 hi/lo splits ----------------
__global__ void conv_split(const float* __restrict__ src, __nv_bfloat16* __restrict__ hi,
                           __nv_bfloat16* __restrict__ lo, size_t n) {
    size_t stride = (size_t)gridDim.x * blockDim.x;
    for (size_t i = (size_t)blockIdx.x * blockDim.x + threadIdx.x; i < n; i += stride) {
        float x = src[i];
        __nv_bfloat16 h = __float2bfloat16(x);
        hi[i] = h;
        lo[i] = __float2bfloat16(x - __bfloat162float(h));
    }
}
__global__ void conv_w(const float* __restrict__ W, __nv_bfloat16* __restrict__ hi,
                       __nv_bfloat16* __restrict__ lo, int K, int NC) {
    int i = blockIdx.x * blockDim.x + threadIdx.x;
    if (i >= K * NC) return;
    int k = i / NC, n = i % NC;
    float x = W[i];
    __nv_bfloat16 h = __float2bfloat16(x);
    hi[(size_t)n * K + k] = h;
    lo[(size_t)n * K + k] = __float2bfloat16(x - __bfloat162float(h));
}

// ---------------- mma.sync helpers ----------------
__device__ __forceinline__ void ldsm_x4(uint32_t* r, uint32_t addr) {
    asm volatile("ldmatrix.sync.aligned.m8n8.x4.shared.b16 {%0,%1,%2,%3}, [%4];"
                 : "=r"(r[0]), "=r"(r[1]), "=r"(r[2]), "=r"(r[3]) : "r"(addr));
}
__device__ __forceinline__ void mma_bf16(float* c, const uint32_t* a, const uint32_t* b) {
    asm volatile("mma.sync.aligned.m16n8k16.row.col.f32.bf16.bf16.f32 "
                 "{%0,%1,%2,%3}, {%4,%5,%6,%7}, {%8,%9}, {%0,%1,%2,%3};"
                 : "+f"(c[0]), "+f"(c[1]), "+f"(c[2]), "+f"(c[3])
                 : "r"(a[0]), "r"(a[1]), "r"(a[2]), "r"(a[3]), "r"(b[0]), "r"(b[1]));
}

// ---------------- HMMA GEMM with register prefetch ----------------
// C[M x NC] = A @ W ; A = Ah+Al, B = Bh+Bl (B stored [NC x K]); drop Al*Bl.
// Block tile 128 x BN, 8 warps. Static smem (one stage), global loads for
// chunk c+1 issued into registers before the compute of chunk c (latency hidden).
template <int BN>
__global__ __launch_bounds__(256)
void hmma_gemm(const __nv_bfloat16* __restrict__ Ah, const __nv_bfloat16* __restrict__ Al,
               const __nv_bfloat16* __restrict__ Bh, const __nv_bfloat16* __restrict__ Bl,
               float* __restrict__ Cout, int M, int K, int NC) {
    constexpr int WN  = BN / 32;
    constexpr int WM  = 8 / WN;
    constexpr int WTM = 128 / WM;
    constexpr int MF  = WTM / 16;
    constexpr int AST = 40;                 // bf16 row stride (80B, conflict-free ldmatrix)
    constexpr int NB  = BN / 64;            // B reg-prefetch iterations

    __shared__ __nv_bfloat16 sAh[128 * AST];
    __shared__ __nv_bfloat16 sAl[128 * AST];
    __shared__ __nv_bfloat16 sBh[BN * AST];
    __shared__ __nv_bfloat16 sBl[BN * AST];

    const int tid  = threadIdx.x;
    const int wid  = tid >> 5, lane = tid & 31;
    const int row0 = blockIdx.y * 128;
    const int bn0  = blockIdx.x * BN;
    const int warpM = wid % WM, warpN = wid / WM;
    const int m0 = warpM * WTM;
    const int n0 = warpN * 32;

    float acc[MF][4][4];
#pragma unroll
    for (int i = 0; i < MF; i++)
#pragma unroll
        for (int j = 0; j < 4; j++)
#pragma unroll
            for (int k = 0; k < 4; k++) acc[i][j][k] = 0.f;

    const int nch = K >> 5;

    uint4 rah[2], ral[2], rbh[NB], rbl[NB];

    // issue global loads for chunk c into registers
    auto ld_regs = [&](int c) {
        const int k0 = c * 32;
#pragma unroll
        for (int it = 0; it < 2; it++) {
            int i = tid + it * 256;               // 0..511
            int r = i >> 2, seg = i & 3;
            int gr = row0 + r; if (gr >= M) gr = M - 1;     // clamp; extra rows never stored to C
            size_t off = (size_t)gr * K + k0 + seg * 8;
            rah[it] = *(const uint4*)(Ah + off);
            ral[it] = *(const uint4*)(Al + off);
        }
#pragma unroll
        for (int it = 0; it < NB; it++) {
            int i = tid + it * 256;
            int r = i >> 2, seg = i & 3;
            size_t off = (size_t)(bn0 + r) * K + k0 + seg * 8;
            rbh[it] = *(const uint4*)(Bh + off);
            rbl[it] = *(const uint4*)(Bl + off);
        }
    };
    // store prefetched registers into smem
    auto st_regs = [&]() {
#pragma unroll
        for (int it = 0; it < 2; it++) {
            int i = tid + it * 256;
            int r = i >> 2, seg = i & 3;
            *(uint4*)&sAh[r * AST + seg * 8] = rah[it];
            *(uint4*)&sAl[r * AST + seg * 8] = ral[it];
        }
#pragma unroll
        for (int it = 0; it < NB; it++) {
            int i = tid + it * 256;
            int r = i >> 2, seg = i & 3;
            *(uint4*)&sBh[r * AST + seg * 8] = rbh[it];
            *(uint4*)&sBl[r * AST + seg * 8] = rbl[it];
        }
    };

    const uint32_t bAh = (uint32_t)__cvta_generic_to_shared(sAh);
    const uint32_t bAl = (uint32_t)__cvta_generic_to_shared(sAl);
    const uint32_t bBh = (uint32_t)__cvta_generic_to_shared(sBh);
    const uint32_t bBl = (uint32_t)__cvta_generic_to_shared(sBl);

    ld_regs(0);

    for (int c = 0; c < nch; c++) {
        st_regs();
        __syncthreads();
        if (c + 1 < nch) ld_regs(c + 1);    // LDGs in flight during compute below

#pragma unroll
        for (int ks = 0; ks < 2; ks++) {
            const int kc = ks * 16;
            uint32_t afh[MF][4], afl[MF][4], bfh[2][4], bfl[2][4];
            int ar = (lane & 15), ak = kc + ((lane >> 4) << 3);
#pragma unroll
            for (int fi = 0; fi < MF; fi++) {
                uint32_t o = (uint32_t)((m0 + fi * 16 + ar) * AST + ak) * 2;
                ldsm_x4(afh[fi], bAh + o);
                ldsm_x4(afl[fi], bAl + o);
            }
            int br = (lane & 7) + ((lane >> 4) << 3), bk = kc + (lane & 8);
#pragma unroll
            for (int g = 0; g < 2; g++) {
                uint32_t o = (uint32_t)((n0 + g * 16 + br) * AST + bk) * 2;
                ldsm_x4(bfh[g], bBh + o);
                ldsm_x4(bfl[g], bBl + o);
            }
#pragma unroll
            for (int fi = 0; fi < MF; fi++)
#pragma unroll
                for (int ni = 0; ni < 4; ni++) {
                    mma_bf16(acc[fi][ni], afh[fi], &bfh[ni >> 1][(ni & 1) * 2]);
                    mma_bf16(acc[fi][ni], afh[fi], &bfl[ni >> 1][(ni & 1) * 2]);
                    mma_bf16(acc[fi][ni], afl[fi], &bfh[ni >> 1][(ni & 1) * 2]);
                }
        }
        __syncthreads();
    }

    const int crow = lane >> 2, ccol = (lane & 3) * 2;
#pragma unroll
    for (int fi = 0; fi < MF; fi++) {
        int r_lo = row0 + m0 + fi * 16 + crow;
        int r_hi = r_lo + 8;
#pragma unroll
        for (int ni = 0; ni < 4; ni++) {
            int c = bn0 + n0 + ni * 8 + ccol;
            if (r_lo < M)
                *(float2*)&Cout[(size_t)r_lo * NC + c] = make_float2(acc[fi][ni][0], acc[fi][ni][1]);
            if (r_hi < M)
                *(float2*)&Cout[(size_t)r_hi * NC + c] = make_float2(acc[fi][ni][2], acc[fi][ni][3]);
        }
    }
}

// ---------------- s/d attention logits: warp per node ----------------
template <int H>
__global__ void sd_kernel(const float* __restrict__ asrc, const float* __restrict__ adst, int N) {
    const int T = H * 64;
    int warp = (blockIdx.x * blockDim.x + threadIdx.x) >> 5;
    int lane = threadIdx.x & 31;
    if (warp >= N) return;
    float as[H], ad[H];
#pragma unroll
    for (int h = 0; h < H; h++) { as[h] = 0.f; ad[h] = 0.f; }
    for (int idx = lane; idx < T; idx += 32) {
        float hv = g_h[(size_t)warp * T + idx];
        int hd = idx >> 6;
        as[hd] += hv * asrc[idx];
        ad[hd] += hv * adst[idx];
    }
#pragma unroll
    for (int h = 0; h < H; h++) {
        float a = as[h], d = ad[h];
        for (int o = 16; o; o >>= 1) {
            a += __shfl_xor_sync(0xffffffffu, a, o);
            d += __shfl_xor_sync(0xffffffffu, d, o);
        }
        if (lane == 0) { g_s[warp * H + h] = a; g_d[warp * H + h] = d; }
    }
}

// ---------------- fused segment softmax + aggregation: warp per destination ----------------
template <int H>
__global__ __launch_bounds__(256) void gat_agg(int N) {
    const int T  = H * 64;
    const int CH = T / 32;
    int warp = (blockIdx.x * blockDim.x + threadIdx.x) >> 5;
    int lane = threadIdx.x & 31;
    if (warp >= N) return;
    int n = warp;

    float sdd[H];
#pragma unroll
    for (int h = 0; h < H; h++) sdd[h] = g_d[n * H + h];

    int r0 = g_rowptr[n], r1 = g_rowptr[n + 1];

    float mx[H];
#pragma unroll
    for (int h = 0; h < H; h++) mx[h] = -1e30f;
    for (int i = r0 + lane; i < r1; i += 32) {
        int s = g_csr[i];
#pragma unroll
        for (int h = 0; h < H; h++) {
            float v = g_s[s * H + h] + sdd[h];
            v = v > 0.f ? v : 0.2f * v;
            mx[h] = fmaxf(mx[h], v);
        }
    }
#pragma unroll
    for (int h = 0; h < H; h++)
        for (int o = 16; o; o >>= 1)
            mx[h] = fmaxf(mx[h], __shfl_xor_sync(0xffffffffu, mx[h], o));

    float den[H];
#pragma unroll
    for (int h = 0; h < H; h++) den[h] = 0.f;
    for (int i = r0 + lane; i < r1; i += 32) {
        int s = g_csr[i];
#pragma unroll
        for (int h = 0; h < H; h++) {
            float v = g_s[s * H + h] + sdd[h];
            v = v > 0.f ? v : 0.2f * v;
            den[h] += expf(v - mx[h]);
        }
    }
#pragma unroll
    for (int h = 0; h < H; h++) {
        for (int o = 16; o; o >>= 1)
            den[h] += __shfl_xor_sync(0xffffffffu, den[h], o);
        den[h] = 1.f / (den[h] + 1e-16f);
    }

    const int myh = (lane * CH) >> 6;
    const float mymx  = mx[myh];
    const float myden = den[myh];
    const float mysdd = sdd[myh];
    float acc[CH];
#pragma unroll
    for (int c = 0; c < CH; c++) acc[c] = 0.f;

    for (int base = r0; base < r1; base += 32) {
        int srcs = (base + lane < r1) ? g_csr[base + lane] : 0;
        int cnt = r1 - base; if (cnt > 32) cnt = 32;
        for (int j = 0; j < cnt; j++) {
            int s = __shfl_sync(0xffffffffu, srcs, j);
            float v = g_s[s * H + myh] + mysdd;
            v = v > 0.f ? v : 0.2f * v;
            float alpha = expf(v - mymx) * myden;
            const float* hp = &g_h[(size_t)s * T + lane * CH];
            if (CH == 8) {
                float4 h0 = *(const float4*)hp;
                float4 h1 = *(const float4*)(hp + 4);
                acc[0] += h0.x * alpha; acc[1] += h0.y * alpha;
                acc[2] += h0.z * alpha; acc[3] += h0.w * alpha;
                acc[4] += h1.x * alpha; acc[5] += h1.y * alpha;
                acc[6] += h1.z * alpha; acc[7] += h1.w * alpha;
            } else {
                float2 h0 = *(const float2*)hp;
                acc[0] += h0.x * alpha; acc[1] += h0.y * alpha;
            }
        }
    }

    float* op = &g_out[(size_t)n * T + lane * CH];
    if (CH == 8) {
        *(float4*)op       = make_float4(acc[0], acc[1], acc[2], acc[3]);
        *(float4*)(op + 4) = make_float4(acc[4], acc[5], acc[6], acc[7]);
    } else {
        *(float2*)op = make_float2(acc[0], acc[1]);
    }
}

// ---------------- batchnorm ----------------
__global__ void bn_init() {
    int c = threadIdx.x;
    g_bnsum[c] = 0.0; g_bnsq[c] = 0.0;
}
__global__ void bn_stats(const float* __restrict__ bias, int C, int N) {
    int rpb = 256 / C;
    int c  = threadIdx.x % C;
    int r0 = blockIdx.x * rpb + threadIdx.x / C;
    double s = 0.0, q = 0.0;
    for (int r = r0; r < N; r += gridDim.x * rpb) {
        float v = g_out[(size_t)r * C + c] + bias[c];
        s += v; q += (double)v * v;
    }
    atomicAdd(&g_bnsum[c], s);
    atomicAdd(&g_bnsq[c], q);
}
__global__ void bn_final(const float* __restrict__ gamma, const float* __restrict__ beta,
                         int C, float inv_n) {
    int c = threadIdx.x;
    if (c >= C) return;
    float mu  = (float)(g_bnsum[c] * inv_n);
    float var = (float)(g_bnsq[c] * inv_n) - mu * mu;
    float sc  = gamma[c] * rsqrtf(var + 1e-5f);
    g_scale[c] = sc;
    g_shift[c] = beta[c] - sc * mu;
}
// apply bn + relu, then emit bf16 hi/lo split directly (feeds next GEMM only)
__global__ void bn_apply_split(const float* __restrict__ bias, int C, int total,
                               __nv_bfloat16* __restrict__ hi, __nv_bfloat16* __restrict__ lo) {
    int stride = gridDim.x * blockDim.x;
    for (int i = blockIdx.x * blockDim.x + threadIdx.x; i < total; i += stride) {
        int c = i & (C - 1);
        float v = g_out[i] + bias[c];
        v = g_scale[c] * v + g_shift[c];
        v = fmaxf(v, 0.f);
        __nv_bfloat16 h = __float2bfloat16(v);
        hi[i] = h;
        lo[i] = __float2bfloat16(v - __bfloat162float(h));
    }
}
__global__ void bn_apply(const float* __restrict__ bias, int C, int total) {
    int stride = gridDim.x * blockDim.x;
    for (int i = blockIdx.x * blockDim.x + threadIdx.x; i < total; i += stride) {
        int c = i & (C - 1);
        float v = g_out[i] + bias[c];
        v = g_scale[c] * v + g_shift[c];
        g_out[i] = fmaxf(v, 0.f);
    }
}

// ---------------- global pooling over N ----------------
__global__ void pool_init() {
    int c = threadIdx.x;
    g_pool_sum[c] = 0.0;
    g_pool_max[c] = 0;
}
__global__ void pool_kernel(int N) {
    __shared__ double ss[64];
    __shared__ int    sm[64];
    int t = threadIdx.x;
    if (t < 64) { ss[t] = 0.0; sm[t] = 0; }
    __syncthreads();
    int c  = t & 63;
    int r0 = blockIdx.x * 4 + (t >> 6);
    double ls = 0.0; float lm = 0.f;
    for (int r = r0; r < N; r += gridDim.x * 4) {
        float v = g_out[(size_t)r * 64 + c];
        ls += v; lm = fmaxf(lm, v);
    }
    atomicAdd(&ss[c], ls);
    atomicMax(&sm[c], __float_as_int(lm));
    __syncthreads();
    if (t < 64) {
        atomicAdd(&g_pool_sum[t], ss[t]);
        atomicMax(&g_pool_max[t], sm[t]);
    }
}

// ---------------- classifier head ----------------
__global__ void classifier(const float* __restrict__ Wc1, const float* __restrict__ bc1,
                           const float* __restrict__ Wc2, const float* __restrict__ bc2,
                           float* __restrict__ out, int N) {
    __shared__ float pooled[128];
    __shared__ float z[64];
    int t = threadIdx.x;
    if (t < 64) pooled[t] = (float)(g_pool_sum[t] / (double)N);
    else        pooled[t] = __int_as_float(g_pool_max[t - 64]);
    __syncthreads();
    if (t < 64) {
        float acc = bc1[t];
        for (int i = 0; i < 128; i++) acc += pooled[i] * Wc1[i * 64 + t];
        z[t] = fmaxf(acc, 0.f);
    }
    __syncthreads();
    if (t < 2) {
        float acc = bc2[t];
        for (int j = 0; j < 64; j++) acc += z[j] * Wc2[j * 2 + t];
        out[t] = acc;
    }
}

// ---------------- launch ----------------
static inline int cdiv(long long a, long long b) { return (int)((a + b - 1) / b); }

extern "C" void kernel_launch(void* const* d_in, const int* in_sizes, int n_in,
                              void* d_out, int out_size) {
    const float* x     = (const float*)d_in[0];
    const void*  ei    = d_in[1];
    const float* W0    = (const float*)d_in[2];
    const float* b0    = (const float*)d_in[3];
    const float* asrc0 = (const float*)d_in[4];
    const float* adst0 = (const float*)d_in[5];
    const float* g0    = (const float*)d_in[6];
    const float* be0   = (const float*)d_in[7];
    const float* W1    = (const float*)d_in[8];
    const float* b1    = (const float*)d_in[9];
    const float* asrc1 = (const float*)d_in[10];
    const float* adst1 = (const float*)d_in[11];
    const float* g1    = (const float*)d_in[12];
    const float* be1   = (const float*)d_in[13];
    const float* W2    = (const float*)d_in[14];
    const float* b2    = (const float*)d_in[15];
    const float* asrc2 = (const float*)d_in[16];
    const float* adst2 = (const float*)d_in[17];
    const float* g2    = (const float*)d_in[18];
    const float* be2   = (const float*)d_in[19];
    const float* Wc1   = (const float*)d_in[20];
    const float* bc1   = (const float*)d_in[21];
    const float* Wc2   = (const float*)d_in[22];
    const float* bc2   = (const float*)d_in[23];

    int N  = in_sizes[0] / 128;
    int E  = in_sizes[1] / 2;
    int ET = E + N;
    float invN = 1.0f / (float)N;

    float* pout = nullptr;
    float* ph   = nullptr;
    __nv_bfloat16 *pAh = nullptr, *pAl = nullptr, *pBh = nullptr, *pBl = nullptr;
    cudaGetSymbolAddress((void**)&pout, g_out);
    cudaGetSymbolAddress((void**)&ph,   g_h);
    cudaGetSymbolAddress((void**)&pAh,  g_Ah);
    cudaGetSymbolAddress((void**)&pAl,  g_Al);
    cudaGetSymbolAddress((void**)&pBh,  g_Bh);
    cudaGetSymbolAddress((void**)&pBl,  g_Bl);

    int gtiles = cdiv(N, 128);
    int nb = cdiv(N, 256);

    detect_kernel<<<1, 32>>>(ei);

    // ---------------- build dst-major CSR once ----------------
    csr_zero<<<cdiv(N, 256), 256>>>(N);
    csr_hist<<<cdiv(ET, 256), 256>>>(ei, E, ET);
    scan1<<<nb, 256>>>(N);
    scan2<<<1, 256>>>(nb);
    scan3<<<nb, 256>>>(N, ET);
    csr_scatter<<<cdiv(ET, 256), 256>>>(ei, E, ET);

    // ---------------- layer 0: Fin=128, H=4, C=64 ----------------
    conv_split<<<2048, 256>>>(x, pAh, pAl, (size_t)N * 128);
    conv_w<<<cdiv(128 * 256, 256), 256>>>(W0, pBh, pBl, 128, 256);
    hmma_gemm<128><<<dim3(2, gtiles), 256>>>(pAh, pAl, pBh, pBl, ph, N, 128, 256);
    sd_kernel<4><<<cdiv((long long)N * 32, 256), 256>>>(asrc0, adst0, N);
    gat_agg<4><<<cdiv((long long)N * 32, 256), 256>>>(N);
    bn_init<<<1, 256>>>();
    bn_stats<<<512, 256>>>(b0, 256, N);
    bn_final<<<1, 256>>>(g0, be0, 256, invN);
    bn_apply_split<<<2048, 256>>>(b0, 256, N * 256, pAh, pAl);

    // ---------------- layer 1: Fin=256, H=4, C=64 ----------------
    conv_w<<<cdiv(256 * 256, 256), 256>>>(W1, pBh, pBl, 256, 256);
    hmma_gemm<128><<<dim3(2, gtiles), 256>>>(pAh, pAl, pBh, pBl, ph, N, 256, 256);
    sd_kernel<4><<<cdiv((long long)N * 32, 256), 256>>>(asrc1, adst1, N);
    gat_agg<4><<<cdiv((long long)N * 32, 256), 256>>>(N);
    bn_init<<<1, 256>>>();
    bn_stats<<<512, 256>>>(b1, 256, N);
    bn_final<<<1, 256>>>(g1, be1, 256, invN);
    bn_apply_split<<<2048, 256>>>(b1, 256, N * 256, pAh, pAl);

    // ---------------- layer 2: Fin=256, H=1, C=64 ----------------
    conv_w<<<cdiv(256 * 64, 256), 256>>>(W2, pBh, pBl, 256, 64);
    hmma_gemm<64><<<dim3(1, gtiles), 256>>>(pAh, pAl, pBh, pBl, ph, N, 256, 64);
    sd_kernel<1><<<cdiv((long long)N * 32, 256), 256>>>(asrc2, adst2, N);
    gat_agg<1><<<cdiv((long long)N * 32, 256), 256>>>(N);
    bn_init<<<1, 256>>>();
    bn_stats<<<512, 256>>>(b2, 64, N);
    bn_final<<<1, 256>>>(g2, be2, 64, invN);
    bn_apply<<<2048, 256>>>(b2, 64, N * 64);

    // ---------------- pooling + classifier ----------------
    pool_init<<<1, 64>>>();
    pool_kernel<<<512, 256>>>(N);
    classifier<<<1, 128>>>(Wc1, bc1, Wc2, bc2, (float*)d_out, N);
}

// round 8
// speedup vs baseline: 1.9038x; 1.0372x over previous
#include <cuda_runtime.h>
#include <cuda_bf16.h>
#include <math.h>
#include <stdint.h>

// ---------------- problem constants ----------------
#define NMAX   50000
#define EMAX   800000
#define ETMAX  (EMAX + NMAX)
#define WD     256
#define HDIM   64

// ---------------- scratch ----------------
__device__ float  g_h  [(size_t)NMAX * WD];
__device__ float  g_out[(size_t)NMAX * WD];
__device__ float  g_s  [NMAX * 4];
__device__ float  g_d  [NMAX * 4];
__device__ double g_bnsum[WD];
__device__ double g_bnsq [WD];
__device__ float  g_scale[WD];
__device__ float  g_shift[WD];
__device__ double g_pool_sum[HDIM];
__device__ int    g_pool_max[HDIM];
__device__ int    g_is64;
__device__ int    g_deg   [NMAX];
__device__ int    g_cursor[NMAX];
__device__ int    g_rowptr[NMAX + 1];
__device__ int    g_csr   [ETMAX];
__device__ int    g_bsum[256];
__device__ int    g_boff[256];
__device__ __nv_bfloat16 g_Ah[(size_t)NMAX * WD];
__device__ __nv_bfloat16 g_Al[(size_t)NMAX * WD];
__device__ __nv_bfloat16 g_Bh[WD * WD];
__device__ __nv_bfloat16 g_Bl[WD * WD];

// ---------------- edge helpers ----------------
__device__ __forceinline__ void get_edge(const void* ei, int e, int E, int& s, int& d) {
    if (e >= E) { s = d = e - E; return; }
    if (g_is64) {
        const long long* p = (const long long*)ei;
        s = (int)p[e]; d = (int)p[(size_t)E + e];
    } else {
        const int* p = (const int*)ei;
        s = p[e]; d = p[E + e];
    }
}

__global__ void detect_kernel(const void* ei) {
    if (threadIdx.x == 0 && blockIdx.x == 0) {
        const unsigned* w = (const unsigned*)ei;
        int is64 = 1;
        for (int i = 0; i < 8; i++)
            if (w[2 * i + 1] != 0u) is64 = 0;
        g_is64 = is64;
    }
}

// ---------------- CSR build ----------------
__global__ void csr_zero(int N) {
    int i = blockIdx.x * blockDim.x + threadIdx.x;
    if (i < N) { g_deg[i] = 0; g_cursor[i] = 0; }
}
__global__ void csr_hist(const void* __restrict__ ei, int E, int ET) {
    int e = blockIdx.x * blockDim.x + threadIdx.x;
    if (e >= ET) return;
    int s, d; get_edge(ei, e, E, s, d);
    atomicAdd(&g_deg[d], 1);
}
__global__ void scan1(int N) {
    __shared__ int sh[256];
    int i = blockIdx.x * 256 + threadIdx.x;
    int v = (i < N) ? g_deg[i] : 0;
    sh[threadIdx.x] = v;
    __syncthreads();
    for (int o = 128; o; o >>= 1) {
        if (threadIdx.x < o) sh[threadIdx.x] += sh[threadIdx.x + o];
        __syncthreads();
    }
    if (threadIdx.x == 0) g_bsum[blockIdx.x] = sh[0];
}
__global__ void scan2(int nb) {
    __shared__ int sh[256];
    int t = threadIdx.x;
    int v = (t < nb) ? g_bsum[t] : 0;
    sh[t] = v;
    __syncthreads();
    for (int o = 1; o < 256; o <<= 1) {
        int u = (t >= o) ? sh[t - o] : 0;
        __syncthreads();
        sh[t] += u;
        __syncthreads();
    }
    g_boff[t] = sh[t] - v;
}
__global__ void scan3(int N, int ET) {
    __shared__ int sh[256];
    int t = threadIdx.x;
    int i = blockIdx.x * 256 + t;
    int v = (i < N) ? g_deg[i] : 0;
    sh[t] = v;
    __syncthreads();
    for (int o = 1; o < 256; o <<= 1) {
        int u = (t >= o) ? sh[t - o] : 0;
        __syncthreads();
        sh[t] += u;
        __syncthreads();
    }
    if (i < N) g_rowptr[i] = g_boff[blockIdx.x] + sh[t] - v;
    if (blockIdx.x == 0 && t == 0) g_rowptr[N] = ET;
}
__global__ void csr_scatter(const void* __restrict__ ei, int E, int ET) {
    int e = blockIdx.x * blockDim.x + threadIdx.x;
    if (e >= ET) return;
    int s, d; get_edge(ei, e, E, s, d);
    int pos = g_rowptr[d] + atomicAdd(&g_cursor[d], 1);
    g_csr[pos] = s;
}

// ---------------- fp32 -> bf16 hi/lo splits ----------------
__global__ void conv_split(const float* __restrict__ src, __nv_bfloat16* __restrict__ hi,
                           __nv_bfloat16* __restrict__ lo, size_t n) {
    size_t stride = (size_t)gridDim.x * blockDim.x;
    for (size_t i = (size_t)blockIdx.x * blockDim.x + threadIdx.x; i < n; i += stride) {
        float x = src[i];
        __nv_bfloat16 h = __float2bfloat16(x);
        hi[i] = h;
        lo[i] = __float2bfloat16(x - __bfloat162float(h));
    }
}
__global__ void conv_w(const float* __restrict__ W, __nv_bfloat16* __restrict__ hi,
                       __nv_bfloat16* __restrict__ lo, int K, int NC) {
    int i = blockIdx.x * blockDim.x + threadIdx.x;
    if (i >= K * NC) return;
    int k = i / NC, n = i % NC;
    float x = W[i];
    __nv_bfloat16 h = __float2bfloat16(x);
    hi[(size_t)n * K + k] = h;
    lo[(size_t)n * K + k] = __float2bfloat16(x - __bfloat162float(h));
}

// ---------------- mma.sync helpers ----------------
__device__ __forceinline__ void ldsm_x4(uint32_t* r, uint32_t addr) {
    asm volatile("ldmatrix.sync.aligned.m8n8.x4.shared.b16 {%0,%1,%2,%3}, [%4];"
                 : "=r"(r[0]), "=r"(r[1]), "=r"(r[2]), "=r"(r[3]) : "r"(addr));
}
__device__ __forceinline__ void mma_bf16(float* c, const uint32_t* a, const uint32_t* b) {
    asm volatile("mma.sync.aligned.m16n8k16.row.col.f32.bf16.bf16.f32 "
                 "{%0,%1,%2,%3}, {%4,%5,%6,%7}, {%8,%9}, {%0,%1,%2,%3};"
                 : "+f"(c[0]), "+f"(c[1]), "+f"(c[2]), "+f"(c[3])
                 : "r"(a[0]), "r"(a[1]), "r"(a[2]), "r"(a[3]), "r"(b[0]), "r"(b[1]));
}

// ---------------- HMMA GEMM with register prefetch ----------------
template <int BN>
__global__ __launch_bounds__(256)
void hmma_gemm(const __nv_bfloat16* __restrict__ Ah, const __nv_bfloat16* __restrict__ Al,
               const __nv_bfloat16* __restrict__ Bh, const __nv_bfloat16* __restrict__ Bl,
               float* __restrict__ Cout, int M, int K, int NC) {
    constexpr int WN  = BN / 32;
    constexpr int WM  = 8 / WN;
    constexpr int WTM = 128 / WM;
    constexpr int MF  = WTM / 16;
    constexpr int AST = 40;
    constexpr int NB  = BN / 64;

    __shared__ __nv_bfloat16 sAh[128 * AST];
    __shared__ __nv_bfloat16 sAl[128 * AST];
    __shared__ __nv_bfloat16 sBh[BN * AST];
    __shared__ __nv_bfloat16 sBl[BN * AST];

    const int tid  = threadIdx.x;
    const int wid  = tid >> 5, lane = tid & 31;
    const int row0 = blockIdx.y * 128;
    const int bn0  = blockIdx.x * BN;
    const int warpM = wid % WM, warpN = wid / WM;
    const int m0 = warpM * WTM;
    const int n0 = warpN * 32;

    float acc[MF][4][4];
#pragma unroll
    for (int i = 0; i < MF; i++)
#pragma unroll
        for (int j = 0; j < 4; j++)
#pragma unroll
            for (int k = 0; k < 4; k++) acc[i][j][k] = 0.f;

    const int nch = K >> 5;

    uint4 rah[2], ral[2], rbh[NB], rbl[NB];

    auto ld_regs = [&](int c) {
        const int k0 = c * 32;
#pragma unroll
        for (int it = 0; it < 2; it++) {
            int i = tid + it * 256;
            int r = i >> 2, seg = i & 3;
            int gr = row0 + r; if (gr >= M) gr = M - 1;
            size_t off = (size_t)gr * K + k0 + seg * 8;
            rah[it] = *(const uint4*)(Ah + off);
            ral[it] = *(const uint4*)(Al + off);
        }
#pragma unroll
        for (int it = 0; it < NB; it++) {
            int i = tid + it * 256;
            int r = i >> 2, seg = i & 3;
            size_t off = (size_t)(bn0 + r) * K + k0 + seg * 8;
            rbh[it] = *(const uint4*)(Bh + off);
            rbl[it] = *(const uint4*)(Bl + off);
        }
    };
    auto st_regs = [&]() {
#pragma unroll
        for (int it = 0; it < 2; it++) {
            int i = tid + it * 256;
            int r = i >> 2, seg = i & 3;
            *(uint4*)&sAh[r * AST + seg * 8] = rah[it];
            *(uint4*)&sAl[r * AST + seg * 8] = ral[it];
        }
#pragma unroll
        for (int it = 0; it < NB; it++) {
            int i = tid + it * 256;
            int r = i >> 2, seg = i & 3;
            *(uint4*)&sBh[r * AST + seg * 8] = rbh[it];
            *(uint4*)&sBl[r * AST + seg * 8] = rbl[it];
        }
    };

    const uint32_t bAh = (uint32_t)__cvta_generic_to_shared(sAh);
    const uint32_t bAl = (uint32_t)__cvta_generic_to_shared(sAl);
    const uint32_t bBh = (uint32_t)__cvta_generic_to_shared(sBh);
    const uint32_t bBl = (uint32_t)__cvta_generic_to_shared(sBl);

    ld_regs(0);

    for (int c = 0; c < nch; c++) {
        st_regs();
        __syncthreads();
        if (c + 1 < nch) ld_regs(c + 1);

#pragma unroll
        for (int ks = 0; ks < 2; ks++) {
            const int kc = ks * 16;
            uint32_t afh[MF][4], afl[MF][4], bfh[2][4], bfl[2][4];
            int ar = (lane & 15), ak = kc + ((lane >> 4) << 3);
#pragma unroll
            for (int fi = 0; fi < MF; fi++) {
                uint32_t o = (uint32_t)((m0 + fi * 16 + ar) * AST + ak) * 2;
                ldsm_x4(afh[fi], bAh + o);
                ldsm_x4(afl[fi], bAl + o);
            }
            int br = (lane & 7) + ((lane >> 4) << 3), bk = kc + (lane & 8);
#pragma unroll
            for (int g = 0; g < 2; g++) {
                uint32_t o = (uint32_t)((n0 + g * 16 + br) * AST + bk) * 2;
                ldsm_x4(bfh[g], bBh + o);
                ldsm_x4(bfl[g], bBl + o);
            }
#pragma unroll
            for (int fi = 0; fi < MF; fi++)
#pragma unroll
                for (int ni = 0; ni < 4; ni++) {
                    mma_bf16(acc[fi][ni], afh[fi], &bfh[ni >> 1][(ni & 1) * 2]);
                    mma_bf16(acc[fi][ni], afh[fi], &bfl[ni >> 1][(ni & 1) * 2]);
                    mma_bf16(acc[fi][ni], afl[fi], &bfh[ni >> 1][(ni & 1) * 2]);
                }
        }
        __syncthreads();
    }

    const int crow = lane >> 2, ccol = (lane & 3) * 2;
#pragma unroll
    for (int fi = 0; fi < MF; fi++) {
        int r_lo = row0 + m0 + fi * 16 + crow;
        int r_hi = r_lo + 8;
#pragma unroll
        for (int ni = 0; ni < 4; ni++) {
            int c = bn0 + n0 + ni * 8 + ccol;
            if (r_lo < M)
                *(float2*)&Cout[(size_t)r_lo * NC + c] = make_float2(acc[fi][ni][0], acc[fi][ni][1]);
            if (r_hi < M)
                *(float2*)&Cout[(size_t)r_hi * NC + c] = make_float2(acc[fi][ni][2], acc[fi][ni][3]);
        }
    }
}

// ---------------- s/d attention logits: warp per node ----------------
template <int H>
__global__ void sd_kernel(const float* __restrict__ asrc, const float* __restrict__ adst, int N) {
    const int T = H * 64;
    int warp = (blockIdx.x * blockDim.x + threadIdx.x) >> 5;
    int lane = threadIdx.x & 31;
    if (warp >= N) return;
    float as[H], ad[H];
#pragma unroll
    for (int h = 0; h < H; h++) { as[h] = 0.f; ad[h] = 0.f; }
    for (int idx = lane; idx < T; idx += 32) {
        float hv = g_h[(size_t)warp * T + idx];
        int hd = idx >> 6;
        as[hd] += hv * asrc[idx];
        ad[hd] += hv * adst[idx];
    }
#pragma unroll
    for (int h = 0; h < H; h++) {
        float a = as[h], d = ad[h];
        for (int o = 16; o; o >>= 1) {
            a += __shfl_xor_sync(0xffffffffu, a, o);
            d += __shfl_xor_sync(0xffffffffu, d, o);
        }
        if (lane == 0) { g_s[warp * H + h] = a; g_d[warp * H + h] = d; }
    }
}

// select from a compile-time register array with runtime index (no spill)
template <int H>
__device__ __forceinline__ float sel(const float (&a)[H], int h) {
    float r = a[0];
#pragma unroll
    for (int i = 1; i < H; i++) r = (h == i) ? a[i] : r;
    return r;
}

// ---------------- fused segment softmax + aggregation: warp per destination ----------------
template <int H>
__global__ __launch_bounds__(256) void gat_agg(int N) {
    const int T  = H * 64;
    const int CH = T / 32;
    int warp = (blockIdx.x * blockDim.x + threadIdx.x) >> 5;
    int lane = threadIdx.x & 31;
    if (warp >= N) return;
    int n = warp;

    float sdd[H];
#pragma unroll
    for (int h = 0; h < H; h++) sdd[h] = g_d[n * H + h];

    int r0 = g_rowptr[n], r1 = g_rowptr[n + 1];

    // pass 1: per-head max
    float mx[H];
#pragma unroll
    for (int h = 0; h < H; h++) mx[h] = -1e30f;
    for (int i = r0 + lane; i < r1; i += 32) {
        int s = g_csr[i];
#pragma unroll
        for (int h = 0; h < H; h++) {
            float v = g_s[s * H + h] + sdd[h];
            v = v > 0.f ? v : 0.2f * v;
            mx[h] = fmaxf(mx[h], v);
        }
    }
#pragma unroll
    for (int h = 0; h < H; h++)
        for (int o = 16; o; o >>= 1)
            mx[h] = fmaxf(mx[h], __shfl_xor_sync(0xffffffffu, mx[h], o));

    // pass 2: per-head denom
    float den[H];
#pragma unroll
    for (int h = 0; h < H; h++) den[h] = 0.f;
    for (int i = r0 + lane; i < r1; i += 32) {
        int s = g_csr[i];
#pragma unroll
        for (int h = 0; h < H; h++) {
            float v = g_s[s * H + h] + sdd[h];
            v = v > 0.f ? v : 0.2f * v;
            den[h] += expf(v - mx[h]);
        }
    }
#pragma unroll
    for (int h = 0; h < H; h++) {
        for (int o = 16; o; o >>= 1)
            den[h] += __shfl_xor_sync(0xffffffffu, den[h], o);
        den[h] = 1.f / (den[h] + 1e-16f);
    }

    // pass 3: weighted aggregation, batched alpha computation
    const int myh = (lane * CH) >> 6;            // head whose channels this lane owns
    // alpha-compute assignment: lane covers edge-in-batch ae, head ah
    const int ah = (H == 4) ? (lane & 3) : 0;
    const int ae = (H == 4) ? (lane >> 2) : lane;
    const float amx  = sel<H>(mx, ah);
    const float aden = sel<H>(den, ah);
    const float asd  = sel<H>(sdd, ah);
    const int EB = (H == 4) ? 8 : 32;            // edges per alpha batch

    float acc[CH];
#pragma unroll
    for (int c = 0; c < CH; c++) acc[c] = 0.f;

    for (int base = r0; base < r1; base += 32) {
        int idx = base + lane;
        int srcs = (idx < r1) ? g_csr[idx] : 0;
        int cnt = r1 - base; if (cnt > 32) cnt = 32;
        for (int b0 = 0; b0 < cnt; b0 += EB) {
            // one exp per lane covers EB edges x H heads
            int sl = __shfl_sync(0xffffffffu, srcs, (b0 + ae) & 31);
            float v = g_s[sl * H + ah] + asd;
            v = v > 0.f ? v : 0.2f * v;
            float alpha = expf(v - amx) * aden;
            int ce = cnt - b0; if (ce > EB) ce = EB;
            for (int e = 0; e < ce; e++) {
                int s  = __shfl_sync(0xffffffffu, srcs, b0 + e);
                float a = (H == 4) ? __shfl_sync(0xffffffffu, alpha, (e << 2) | myh)
                                   : __shfl_sync(0xffffffffu, alpha, e);
                const float* hp = &g_h[(size_t)s * T + lane * CH];
                if (CH == 8) {
                    float4 h0 = *(const float4*)hp;
                    float4 h1 = *(const float4*)(hp + 4);
                    acc[0] += h0.x * a; acc[1] += h0.y * a;
                    acc[2] += h0.z * a; acc[3] += h0.w * a;
                    acc[4] += h1.x * a; acc[5] += h1.y * a;
                    acc[6] += h1.z * a; acc[7] += h1.w * a;
                } else {
                    float2 h0 = *(const float2*)hp;
                    acc[0] += h0.x * a; acc[1] += h0.y * a;
                }
            }
        }
    }

    float* op = &g_out[(size_t)n * T + lane * CH];
    if (CH == 8) {
        *(float4*)op       = make_float4(acc[0], acc[1], acc[2], acc[3]);
        *(float4*)(op + 4) = make_float4(acc[4], acc[5], acc[6], acc[7]);
    } else {
        *(float2*)op = make_float2(acc[0], acc[1]);
    }
}

// ---------------- batchnorm ----------------
__global__ void bn_init() {
    int c = threadIdx.x;
    g_bnsum[c] = 0.0; g_bnsq[c] = 0.0;
}
__global__ void bn_stats(const float* __restrict__ bias, int C, int N) {
    int rpb = 256 / C;
    int c  = threadIdx.x % C;
    int r0 = blockIdx.x * rpb + threadIdx.x / C;
    double s = 0.0, q = 0.0;
    for (int r = r0; r < N; r += gridDim.x * rpb) {
        float v = g_out[(size_t)r * C + c] + bias[c];
        s += v; q += (double)v * v;
    }
    atomicAdd(&g_bnsum[c], s);
    atomicAdd(&g_bnsq[c], q);
}
__global__ void bn_final(const float* __restrict__ gamma, const float* __restrict__ beta,
                         int C, float inv_n) {
    int c = threadIdx.x;
    if (c >= C) return;
    float mu  = (float)(g_bnsum[c] * inv_n);
    float var = (float)(g_bnsq[c] * inv_n) - mu * mu;
    float sc  = gamma[c] * rsqrtf(var + 1e-5f);
    g_scale[c] = sc;
    g_shift[c] = beta[c] - sc * mu;
}
// apply bn + relu, emit bf16 hi/lo split (feeds next GEMM)
__global__ void bn_apply_split(const float* __restrict__ bias, int C, int total,
                               __nv_bfloat16* __restrict__ hi, __nv_bfloat16* __restrict__ lo) {
    int stride = gridDim.x * blockDim.x;
    for (int i = blockIdx.x * blockDim.x + threadIdx.x; i < total; i += stride) {
        int c = i & (C - 1);
        float v = g_out[i] + bias[c];
        v = g_scale[c] * v + g_shift[c];
        v = fmaxf(v, 0.f);
        __nv_bfloat16 h = __float2bfloat16(v);
        hi[i] = h;
        lo[i] = __float2bfloat16(v - __bfloat162float(h));
    }
}
// layer 2: apply bn + relu, write g_out AND accumulate global pool sums/max
__global__ void bn_apply_pool(const float* __restrict__ bias, int total) {
    __shared__ float ssum[64];
    __shared__ int   smax[64];
    int t = threadIdx.x;
    if (t < 64) { ssum[t] = 0.f; smax[t] = 0; }
    __syncthreads();
    int stride = gridDim.x * blockDim.x;        // multiple of 64
    float lsum = 0.f, lmax = 0.f;
    int c = (blockIdx.x * blockDim.x + t) & 63;
    for (int i = blockIdx.x * blockDim.x + t; i < total; i += stride) {
        float v = g_out[i] + bias[c];
        v = g_scale[c] * v + g_shift[c];
        v = fmaxf(v, 0.f);
        g_out[i] = v;
        lsum += v; lmax = fmaxf(lmax, v);
    }
    atomicAdd(&ssum[t & 63], lsum);
    atomicMax(&smax[t & 63], __float_as_int(lmax));
    __syncthreads();
    if (t < 64) {
        atomicAdd(&g_pool_sum[t], (double)ssum[t]);
        atomicMax(&g_pool_max[t], smax[t]);
    }
}

// ---------------- pooling init + classifier ----------------
__global__ void pool_init() {
    int c = threadIdx.x;
    g_pool_sum[c] = 0.0;
    g_pool_max[c] = 0;
}
__global__ void classifier(const float* __restrict__ Wc1, const float* __restrict__ bc1,
                           const float* __restrict__ Wc2, const float* __restrict__ bc2,
                           float* __restrict__ out, int N) {
    __shared__ float pooled[128];
    __shared__ float z[64];
    int t = threadIdx.x;
    if (t < 64) pooled[t] = (float)(g_pool_sum[t] / (double)N);
    else        pooled[t] = __int_as_float(g_pool_max[t - 64]);
    __syncthreads();
    if (t < 64) {
        float acc = bc1[t];
        for (int i = 0; i < 128; i++) acc += pooled[i] * Wc1[i * 64 + t];
        z[t] = fmaxf(acc, 0.f);
    }
    __syncthreads();
    if (t < 2) {
        float acc = bc2[t];
        for (int j = 0; j < 64; j++) acc += z[j] * Wc2[j * 2 + t];
        out[t] = acc;
    }
}

// ---------------- launch ----------------
static inline int cdiv(long long a, long long b) { return (int)((a + b - 1) / b); }

extern "C" void kernel_launch(void* const* d_in, const int* in_sizes, int n_in,
                              void* d_out, int out_size) {
    const float* x     = (const float*)d_in[0];
    const void*  ei    = d_in[1];
    const float* W0    = (const float*)d_in[2];
    const float* b0    = (const float*)d_in[3];
    const float* asrc0 = (const float*)d_in[4];
    const float* adst0 = (const float*)d_in[5];
    const float* g0    = (const float*)d_in[6];
    const float* be0   = (const float*)d_in[7];
    const float* W1    = (const float*)d_in[8];
    const float* b1    = (const float*)d_in[9];
    const float* asrc1 = (const float*)d_in[10];
    const float* adst1 = (const float*)d_in[11];
    const float* g1    = (const float*)d_in[12];
    const float* be1   = (const float*)d_in[13];
    const float* W2    = (const float*)d_in[14];
    const float* b2    = (const float*)d_in[15];
    const float* asrc2 = (const float*)d_in[16];
    const float* adst2 = (const float*)d_in[17];
    const float* g2    = (const float*)d_in[18];
    const float* be2   = (const float*)d_in[19];
    const float* Wc1   = (const float*)d_in[20];
    const float* bc1   = (const float*)d_in[21];
    const float* Wc2   = (const float*)d_in[22];
    const float* bc2   = (const float*)d_in[23];

    int N  = in_sizes[0] / 128;
    int E  = in_sizes[1] / 2;
    int ET = E + N;
    float invN = 1.0f / (float)N;

    float* pout = nullptr;
    float* ph   = nullptr;
    __nv_bfloat16 *pAh = nullptr, *pAl = nullptr, *pBh = nullptr, *pBl = nullptr;
    cudaGetSymbolAddress((void**)&pout, g_out);
    cudaGetSymbolAddress((void**)&ph,   g_h);
    cudaGetSymbolAddress((void**)&pAh,  g_Ah);
    cudaGetSymbolAddress((void**)&pAl,  g_Al);
    cudaGetSymbolAddress((void**)&pBh,  g_Bh);
    cudaGetSymbolAddress((void**)&pBl,  g_Bl);

    int gtiles = cdiv(N, 128);
    int nb = cdiv(N, 256);

    // ---------------- layer 0 GEMM first (4th launch -> ncu capture window) ----
    detect_kernel<<<1, 32>>>(ei);
    conv_split<<<2048, 256>>>(x, pAh, pAl, (size_t)N * 128);
    conv_w<<<cdiv(128 * 256, 256), 256>>>(W0, pBh, pBl, 128, 256);
    hmma_gemm<128><<<dim3(2, gtiles), 256>>>(pAh, pAl, pBh, pBl, ph, N, 128, 256);

    // ---------------- build dst-major CSR (reused by all 3 layers) ------------
    csr_zero<<<cdiv(N, 256), 256>>>(N);
    csr_hist<<<cdiv(ET, 256), 256>>>(ei, E, ET);
    scan1<<<nb, 256>>>(N);
    scan2<<<1, 256>>>(nb);
    scan3<<<nb, 256>>>(N, ET);
    csr_scatter<<<cdiv(ET, 256), 256>>>(ei, E, ET);

    // ---------------- layer 0 rest: H=4, C=64 ----------------
    sd_kernel<4><<<cdiv((long long)N * 32, 256), 256>>>(asrc0, adst0, N);
    gat_agg<4><<<cdiv((long long)N * 32, 256), 256>>>(N);
    bn_init<<<1, 256>>>();
    bn_stats<<<512, 256>>>(b0, 256, N);
    bn_final<<<1, 256>>>(g0, be0, 256, invN);
    bn_apply_split<<<2048, 256>>>(b0, 256, N * 256, pAh, pAl);

    // ---------------- layer 1: Fin=256, H=4, C=64 ----------------
    conv_w<<<cdiv(256 * 256, 256), 256>>>(W1, pBh, pBl, 256, 256);
    hmma_gemm<128><<<dim3(2, gtiles), 256>>>(pAh, pAl, pBh, pBl, ph, N, 256, 256);
    sd_kernel<4><<<cdiv((long long)N * 32, 256), 256>>>(asrc1, adst1, N);
    gat_agg<4><<<cdiv((long long)N * 32, 256), 256>>>(N);
    bn_init<<<1, 256>>>();
    bn_stats<<<512, 256>>>(b1, 256, N);
    bn_final<<<1, 256>>>(g1, be1, 256, invN);
    bn_apply_split<<<2048, 256>>>(b1, 256, N * 256, pAh, pAl);

    // ---------------- layer 2: Fin=256, H=1, C=64 ----------------
    conv_w<<<cdiv(256 * 64, 256), 256>>>(W2, pBh, pBl, 256, 64);
    hmma_gemm<64><<<dim3(1, gtiles), 256>>>(pAh, pAl, pBh, pBl, ph, N, 256, 64);
    sd_kernel<1><<<cdiv((long long)N * 32, 256), 256>>>(asrc2, adst2, N);
    gat_agg<1><<<cdiv((long long)N * 32, 256), 256>>>(N);
    bn_init<<<1, 256>>>();
    bn_stats<<<512, 256>>>(b2, 64, N);
    bn_final<<<1, 256>>>(g2, be2, 64, invN);
    pool_init<<<1, 64>>>();
    bn_apply_pool<<<2048, 256>>>(b2, N * 64);

    // ---------------- classifier ----------------
    classifier<<<1, 128>>>(Wc1, bc1, Wc2, bc2, (float*)d_out, N);
}

// round 9
// speedup vs baseline: 2.0165x; 1.0592x over previous
#include <cuda_runtime.h>
#include <cuda_bf16.h>
#include <math.h>
#include <stdint.h>

// ---------------- problem constants ----------------
#define NMAX   50000
#define EMAX   800000
#define ETMAX  (EMAX + NMAX)
#define WD     256
#define HDIM   64

// ---------------- scratch ----------------
__device__ float  g_h  [(size_t)NMAX * WD];
__device__ float  g_out[(size_t)NMAX * WD];
__device__ float  g_s  [NMAX * 4];
__device__ float  g_d  [NMAX * 4];
__device__ double g_bnsum[WD];
__device__ double g_bnsq [WD];
__device__ float  g_scale[WD];
__device__ float  g_shift[WD];
__device__ double g_pool_sum[HDIM];
__device__ int    g_pool_max[HDIM];
__device__ int    g_is64;
__device__ int    g_deg   [NMAX];
__device__ int    g_cursor[NMAX];
__device__ int    g_rowptr[NMAX + 1];
__device__ int    g_csr   [ETMAX];
__device__ int    g_bsum[256];
__device__ int    g_boff[256];
__device__ __nv_bfloat16 g_Ah[(size_t)NMAX * WD];
__device__ __nv_bfloat16 g_Al[(size_t)NMAX * WD];
__device__ __nv_bfloat16 g_Bh[WD * WD];
__device__ __nv_bfloat16 g_Bl[WD * WD];

// ---------------- edge helpers ----------------
__device__ __forceinline__ void get_edge(const void* ei, int e, int E, int& s, int& d) {
    if (e >= E) { s = d = e - E; return; }
    if (g_is64) {
        const long long* p = (const long long*)ei;
        s = (int)p[e]; d = (int)p[(size_t)E + e];
    } else {
        const int* p = (const int*)ei;
        s = p[e]; d = p[E + e];
    }
}

__global__ void detect_kernel(const void* ei) {
    if (threadIdx.x == 0 && blockIdx.x == 0) {
        const unsigned* w = (const unsigned*)ei;
        int is64 = 1;
        for (int i = 0; i < 8; i++)
            if (w[2 * i + 1] != 0u) is64 = 0;
        g_is64 = is64;
    }
}

// ---------------- CSR build ----------------
__global__ void csr_zero(int N) {
    int i = blockIdx.x * blockDim.x + threadIdx.x;
    if (i < N) { g_deg[i] = 0; g_cursor[i] = 0; }
}
__global__ void csr_hist(const void* __restrict__ ei, int E, int ET) {
    int e = blockIdx.x * blockDim.x + threadIdx.x;
    if (e >= ET) return;
    int s, d; get_edge(ei, e, E, s, d);
    atomicAdd(&g_deg[d], 1);
}
__global__ void scan1(int N) {
    __shared__ int sh[256];
    int i = blockIdx.x * 256 + threadIdx.x;
    int v = (i < N) ? g_deg[i] : 0;
    sh[threadIdx.x] = v;
    __syncthreads();
    for (int o = 128; o; o >>= 1) {
        if (threadIdx.x < o) sh[threadIdx.x] += sh[threadIdx.x + o];
        __syncthreads();
    }
    if (threadIdx.x == 0) g_bsum[blockIdx.x] = sh[0];
}
__global__ void scan2(int nb) {
    __shared__ int sh[256];
    int t = threadIdx.x;
    int v = (t < nb) ? g_bsum[t] : 0;
    sh[t] = v;
    __syncthreads();
    for (int o = 1; o < 256; o <<= 1) {
        int u = (t >= o) ? sh[t - o] : 0;
        __syncthreads();
        sh[t] += u;
        __syncthreads();
    }
    g_boff[t] = sh[t] - v;
}
__global__ void scan3(int N, int ET) {
    __shared__ int sh[256];
    int t = threadIdx.x;
    int i = blockIdx.x * 256 + t;
    int v = (i < N) ? g_deg[i] : 0;
    sh[t] = v;
    __syncthreads();
    for (int o = 1; o < 256; o <<= 1) {
        int u = (t >= o) ? sh[t - o] : 0;
        __syncthreads();
        sh[t] += u;
        __syncthreads();
    }
    if (i < N) g_rowptr[i] = g_boff[blockIdx.x] + sh[t] - v;
    if (blockIdx.x == 0 && t == 0) g_rowptr[N] = ET;
}
__global__ void csr_scatter(const void* __restrict__ ei, int E, int ET) {
    int e = blockIdx.x * blockDim.x + threadIdx.x;
    if (e >= ET) return;
    int s, d; get_edge(ei, e, E, s, d);
    int pos = g_rowptr[d] + atomicAdd(&g_cursor[d], 1);
    g_csr[pos] = s;
}

// ---------------- fp32 -> bf16 hi/lo splits ----------------
__global__ void conv_split(const float* __restrict__ src, __nv_bfloat16* __restrict__ hi,
                           __nv_bfloat16* __restrict__ lo, size_t n) {
    size_t stride = (size_t)gridDim.x * blockDim.x;
    for (size_t i = (size_t)blockIdx.x * blockDim.x + threadIdx.x; i < n; i += stride) {
        float x = src[i];
        __nv_bfloat16 h = __float2bfloat16(x);
        hi[i] = h;
        lo[i] = __float2bfloat16(x - __bfloat162float(h));
    }
}
__global__ void conv_w(const float* __restrict__ W, __nv_bfloat16* __restrict__ hi,
                       __nv_bfloat16* __restrict__ lo, int K, int NC) {
    int i = blockIdx.x * blockDim.x + threadIdx.x;
    if (i >= K * NC) return;
    int k = i / NC, n = i % NC;
    float x = W[i];
    __nv_bfloat16 h = __float2bfloat16(x);
    hi[(size_t)n * K + k] = h;
    lo[(size_t)n * K + k] = __float2bfloat16(x - __bfloat162float(h));
}

// zero g_s/g_d before fused-sd GEMM
__global__ void zero_sd(int nh) {
    int i = blockIdx.x * blockDim.x + threadIdx.x;
    if (i < nh) { g_s[i] = 0.f; g_d[i] = 0.f; }
}

// ---------------- mma.sync helpers ----------------
__device__ __forceinline__ void ldsm_x4(uint32_t* r, uint32_t addr) {
    asm volatile("ldmatrix.sync.aligned.m8n8.x4.shared.b16 {%0,%1,%2,%3}, [%4];"
                 : "=r"(r[0]), "=r"(r[1]), "=r"(r[2]), "=r"(r[3]) : "r"(addr));
}
__device__ __forceinline__ void mma_bf16(float* c, const uint32_t* a, const uint32_t* b) {
    asm volatile("mma.sync.aligned.m16n8k16.row.col.f32.bf16.bf16.f32 "
                 "{%0,%1,%2,%3}, {%4,%5,%6,%7}, {%8,%9}, {%0,%1,%2,%3};"
                 : "+f"(c[0]), "+f"(c[1]), "+f"(c[2]), "+f"(c[3])
                 : "r"(a[0]), "r"(a[1]), "r"(a[2]), "r"(a[3]), "r"(b[0]), "r"(b[1]));
}

// ---------------- HMMA GEMM, 2 CTAs/SM, fused s/d epilogue ----------------
// C[M x NC] = A @ W ; A = Ah+Al, B = Bh+Bl (B stored [NC x K]); drop Al*Bl.
// Block tile 128 x BN, 8 warps, plain synchronous tile loads; 2 co-resident
// CTAs hide each other's load/sync phases. Epilogue also emits partial
// s = C.asrc, d = C.adst per (row, head) via atomics.
template <int BN>
__global__ __launch_bounds__(256, 2)
void hmma_gemm(const __nv_bfloat16* __restrict__ Ah, const __nv_bfloat16* __restrict__ Al,
               const __nv_bfloat16* __restrict__ Bh, const __nv_bfloat16* __restrict__ Bl,
               float* __restrict__ Cout, int M, int K, int NC, int H,
               const float* __restrict__ asrc, const float* __restrict__ adst) {
    constexpr int WN  = BN / 32;
    constexpr int WM  = 8 / WN;
    constexpr int WTM = 128 / WM;
    constexpr int MF  = WTM / 16;
    constexpr int AST = 40;
    constexpr int NB  = BN / 64;

    __shared__ __nv_bfloat16 sAh[128 * AST];
    __shared__ __nv_bfloat16 sAl[128 * AST];
    __shared__ __nv_bfloat16 sBh[BN * AST];
    __shared__ __nv_bfloat16 sBl[BN * AST];

    const int tid  = threadIdx.x;
    const int wid  = tid >> 5, lane = tid & 31;
    const int row0 = blockIdx.y * 128;
    const int bn0  = blockIdx.x * BN;
    const int warpM = wid % WM, warpN = wid / WM;
    const int m0 = warpM * WTM;
    const int n0 = warpN * 32;

    float acc[MF][4][4];
#pragma unroll
    for (int i = 0; i < MF; i++)
#pragma unroll
        for (int j = 0; j < 4; j++)
#pragma unroll
            for (int k = 0; k < 4; k++) acc[i][j][k] = 0.f;

    const int nch = K >> 5;

    const uint32_t bAh = (uint32_t)__cvta_generic_to_shared(sAh);
    const uint32_t bAl = (uint32_t)__cvta_generic_to_shared(sAl);
    const uint32_t bBh = (uint32_t)__cvta_generic_to_shared(sBh);
    const uint32_t bBl = (uint32_t)__cvta_generic_to_shared(sBl);

    for (int c = 0; c < nch; c++) {
        const int k0 = c * 32;
        __syncthreads();                      // previous compute done, buffers free
#pragma unroll
        for (int it = 0; it < 2; it++) {
            int i = tid + it * 256;
            int r = i >> 2, seg = i & 3;
            int gr = row0 + r; if (gr >= M) gr = M - 1;
            size_t off = (size_t)gr * K + k0 + seg * 8;
            *(uint4*)&sAh[r * AST + seg * 8] = *(const uint4*)(Ah + off);
            *(uint4*)&sAl[r * AST + seg * 8] = *(const uint4*)(Al + off);
        }
#pragma unroll
        for (int it = 0; it < NB; it++) {
            int i = tid + it * 256;
            int r = i >> 2, seg = i & 3;
            size_t off = (size_t)(bn0 + r) * K + k0 + seg * 8;
            *(uint4*)&sBh[r * AST + seg * 8] = *(const uint4*)(Bh + off);
            *(uint4*)&sBl[r * AST + seg * 8] = *(const uint4*)(Bl + off);
        }
        __syncthreads();

#pragma unroll
        for (int ks = 0; ks < 2; ks++) {
            const int kc = ks * 16;
            uint32_t afh[MF][4], afl[MF][4], bfh[2][4], bfl[2][4];
            int ar = (lane & 15), ak = kc + ((lane >> 4) << 3);
#pragma unroll
            for (int fi = 0; fi < MF; fi++) {
                uint32_t o = (uint32_t)((m0 + fi * 16 + ar) * AST + ak) * 2;
                ldsm_x4(afh[fi], bAh + o);
                ldsm_x4(afl[fi], bAl + o);
            }
            int br = (lane & 7) + ((lane >> 4) << 3), bk = kc + (lane & 8);
#pragma unroll
            for (int g = 0; g < 2; g++) {
                uint32_t o = (uint32_t)((n0 + g * 16 + br) * AST + bk) * 2;
                ldsm_x4(bfh[g], bBh + o);
                ldsm_x4(bfl[g], bBl + o);
            }
#pragma unroll
            for (int fi = 0; fi < MF; fi++)
#pragma unroll
                for (int ni = 0; ni < 4; ni++) {
                    mma_bf16(acc[fi][ni], afh[fi], &bfh[ni >> 1][(ni & 1) * 2]);
                    mma_bf16(acc[fi][ni], afh[fi], &bfl[ni >> 1][(ni & 1) * 2]);
                    mma_bf16(acc[fi][ni], afl[fi], &bfh[ni >> 1][(ni & 1) * 2]);
                }
        }
    }

    // ---- epilogue: store C and fused s/d partial dot products ----
    const int crow = lane >> 2, ccol = (lane & 3) * 2;
    const int head = (bn0 + n0) >> 6;               // warp's cols live in ONE head
    float2 avs[4], avd[4];
#pragma unroll
    for (int ni = 0; ni < 4; ni++) {
        int cc = bn0 + n0 + ni * 8 + ccol;
        avs[ni] = *(const float2*)&asrc[cc];
        avd[ni] = *(const float2*)&adst[cc];
    }
#pragma unroll
    for (int fi = 0; fi < MF; fi++) {
        int r_lo = row0 + m0 + fi * 16 + crow;
        int r_hi = r_lo + 8;
        float sl = 0.f, dl = 0.f, sh = 0.f, dh = 0.f;
#pragma unroll
        for (int ni = 0; ni < 4; ni++) {
            int c = bn0 + n0 + ni * 8 + ccol;
            if (r_lo < M)
                *(float2*)&Cout[(size_t)r_lo * NC + c] = make_float2(acc[fi][ni][0], acc[fi][ni][1]);
            if (r_hi < M)
                *(float2*)&Cout[(size_t)r_hi * NC + c] = make_float2(acc[fi][ni][2], acc[fi][ni][3]);
            sl += acc[fi][ni][0] * avs[ni].x + acc[fi][ni][1] * avs[ni].y;
            dl += acc[fi][ni][0] * avd[ni].x + acc[fi][ni][1] * avd[ni].y;
            sh += acc[fi][ni][2] * avs[ni].x + acc[fi][ni][3] * avs[ni].y;
            dh += acc[fi][ni][2] * avd[ni].x + acc[fi][ni][3] * avd[ni].y;
        }
        // reduce over the 4 lanes (ccol groups) that hold this row
#pragma unroll
        for (int o = 1; o <= 2; o <<= 1) {
            sl += __shfl_xor_sync(0xffffffffu, sl, o);
            dl += __shfl_xor_sync(0xffffffffu, dl, o);
            sh += __shfl_xor_sync(0xffffffffu, sh, o);
            dh += __shfl_xor_sync(0xffffffffu, dh, o);
        }
        if ((lane & 3) == 0) {
            if (r_lo < M) {
                atomicAdd(&g_s[r_lo * H + head], sl);
                atomicAdd(&g_d[r_lo * H + head], dl);
            }
            if (r_hi < M) {
                atomicAdd(&g_s[r_hi * H + head], sh);
                atomicAdd(&g_d[r_hi * H + head], dh);
            }
        }
    }
}

// select from a compile-time register array with runtime index (no spill)
template <int H>
__device__ __forceinline__ float sel(const float (&a)[H], int h) {
    float r = a[0];
#pragma unroll
    for (int i = 1; i < H; i++) r = (h == i) ? a[i] : r;
    return r;
}

// ---------------- fused segment softmax + aggregation: warp per destination ----------------
template <int H>
__global__ __launch_bounds__(256) void gat_agg(int N) {
    const int T  = H * 64;
    const int CH = T / 32;
    int warp = (blockIdx.x * blockDim.x + threadIdx.x) >> 5;
    int lane = threadIdx.x & 31;
    if (warp >= N) return;
    int n = warp;

    float sdd[H];
#pragma unroll
    for (int h = 0; h < H; h++) sdd[h] = g_d[n * H + h];

    int r0 = g_rowptr[n], r1 = g_rowptr[n + 1];

    float mx[H];
#pragma unroll
    for (int h = 0; h < H; h++) mx[h] = -1e30f;
    for (int i = r0 + lane; i < r1; i += 32) {
        int s = g_csr[i];
#pragma unroll
        for (int h = 0; h < H; h++) {
            float v = g_s[s * H + h] + sdd[h];
            v = v > 0.f ? v : 0.2f * v;
            mx[h] = fmaxf(mx[h], v);
        }
    }
#pragma unroll
    for (int h = 0; h < H; h++)
        for (int o = 16; o; o >>= 1)
            mx[h] = fmaxf(mx[h], __shfl_xor_sync(0xffffffffu, mx[h], o));

    float den[H];
#pragma unroll
    for (int h = 0; h < H; h++) den[h] = 0.f;
    for (int i = r0 + lane; i < r1; i += 32) {
        int s = g_csr[i];
#pragma unroll
        for (int h = 0; h < H; h++) {
            float v = g_s[s * H + h] + sdd[h];
            v = v > 0.f ? v : 0.2f * v;
            den[h] += expf(v - mx[h]);
        }
    }
#pragma unroll
    for (int h = 0; h < H; h++) {
        for (int o = 16; o; o >>= 1)
            den[h] += __shfl_xor_sync(0xffffffffu, den[h], o);
        den[h] = 1.f / (den[h] + 1e-16f);
    }

    const int myh = (lane * CH) >> 6;
    const int ah = (H == 4) ? (lane & 3) : 0;
    const int ae = (H == 4) ? (lane >> 2) : lane;
    const float amx  = sel<H>(mx, ah);
    const float aden = sel<H>(den, ah);
    const float asd  = sel<H>(sdd, ah);
    const int EB = (H == 4) ? 8 : 32;

    float acc[CH];
#pragma unroll
    for (int c = 0; c < CH; c++) acc[c] = 0.f;

    for (int base = r0; base < r1; base += 32) {
        int idx = base + lane;
        int srcs = (idx < r1) ? g_csr[idx] : 0;
        int cnt = r1 - base; if (cnt > 32) cnt = 32;
        for (int b0 = 0; b0 < cnt; b0 += EB) {
            int sl = __shfl_sync(0xffffffffu, srcs, (b0 + ae) & 31);
            float v = g_s[sl * H + ah] + asd;
            v = v > 0.f ? v : 0.2f * v;
            float alpha = expf(v - amx) * aden;
            int ce = cnt - b0; if (ce > EB) ce = EB;
            for (int e = 0; e < ce; e++) {
                int s  = __shfl_sync(0xffffffffu, srcs, b0 + e);
                float a = (H == 4) ? __shfl_sync(0xffffffffu, alpha, (e << 2) | myh)
                                   : __shfl_sync(0xffffffffu, alpha, e);
                const float* hp = &g_h[(size_t)s * T + lane * CH];
                if (CH == 8) {
                    float4 h0 = *(const float4*)hp;
                    float4 h1 = *(const float4*)(hp + 4);
                    acc[0] += h0.x * a; acc[1] += h0.y * a;
                    acc[2] += h0.z * a; acc[3] += h0.w * a;
                    acc[4] += h1.x * a; acc[5] += h1.y * a;
                    acc[6] += h1.z * a; acc[7] += h1.w * a;
                } else {
                    float2 h0 = *(const float2*)hp;
                    acc[0] += h0.x * a; acc[1] += h0.y * a;
                }
            }
        }
    }

    float* op = &g_out[(size_t)n * T + lane * CH];
    if (CH == 8) {
        *(float4*)op       = make_float4(acc[0], acc[1], acc[2], acc[3]);
        *(float4*)(op + 4) = make_float4(acc[4], acc[5], acc[6], acc[7]);
    } else {
        *(float2*)op = make_float2(acc[0], acc[1]);
    }
}

// ---------------- batchnorm ----------------
__global__ void bn_init() {
    int c = threadIdx.x;
    g_bnsum[c] = 0.0; g_bnsq[c] = 0.0;
}
__global__ void bn_stats(const float* __restrict__ bias, int C, int N) {
    int rpb = 256 / C;
    int c  = threadIdx.x % C;
    int r0 = blockIdx.x * rpb + threadIdx.x / C;
    double s = 0.0, q = 0.0;
    for (int r = r0; r < N; r += gridDim.x * rpb) {
        float v = g_out[(size_t)r * C + c] + bias[c];
        s += v; q += (double)v * v;
    }
    atomicAdd(&g_bnsum[c], s);
    atomicAdd(&g_bnsq[c], q);
}
__global__ void bn_final(const float* __restrict__ gamma, const float* __restrict__ beta,
                         int C, float inv_n) {
    int c = threadIdx.x;
    if (c >= C) return;
    float mu  = (float)(g_bnsum[c] * inv_n);
    float var = (float)(g_bnsq[c] * inv_n) - mu * mu;
    float sc  = gamma[c] * rsqrtf(var + 1e-5f);
    g_scale[c] = sc;
    g_shift[c] = beta[c] - sc * mu;
}
__global__ void bn_apply_split(const float* __restrict__ bias, int C, int total,
                               __nv_bfloat16* __restrict__ hi, __nv_bfloat16* __restrict__ lo) {
    int stride = gridDim.x * blockDim.x;
    for (int i = blockIdx.x * blockDim.x + threadIdx.x; i < total; i += stride) {
        int c = i & (C - 1);
        float v = g_out[i] + bias[c];
        v = g_scale[c] * v + g_shift[c];
        v = fmaxf(v, 0.f);
        __nv_bfloat16 h = __float2bfloat16(v);
        hi[i] = h;
        lo[i] = __float2bfloat16(v - __bfloat162float(h));
    }
}
__global__ void bn_apply_pool(const float* __restrict__ bias, int total) {
    __shared__ float ssum[64];
    __shared__ int   smax[64];
    int t = threadIdx.x;
    if (t < 64) { ssum[t] = 0.f; smax[t] = 0; }
    __syncthreads();
    int stride = gridDim.x * blockDim.x;
    float lsum = 0.f, lmax = 0.f;
    int c = (blockIdx.x * blockDim.x + t) & 63;
    for (int i = blockIdx.x * blockDim.x + t; i < total; i += stride) {
        float v = g_out[i] + bias[c];
        v = g_scale[c] * v + g_shift[c];
        v = fmaxf(v, 0.f);
        g_out[i] = v;
        lsum += v; lmax = fmaxf(lmax, v);
    }
    atomicAdd(&ssum[t & 63], lsum);
    atomicMax(&smax[t & 63], __float_as_int(lmax));
    __syncthreads();
    if (t < 64) {
        atomicAdd(&g_pool_sum[t], (double)ssum[t]);
        atomicMax(&g_pool_max[t], smax[t]);
    }
}

// ---------------- pooling init + classifier ----------------
__global__ void pool_init() {
    int c = threadIdx.x;
    g_pool_sum[c] = 0.0;
    g_pool_max[c] = 0;
}
__global__ void classifier(const float* __restrict__ Wc1, const float* __restrict__ bc1,
                           const float* __restrict__ Wc2, const float* __restrict__ bc2,
                           float* __restrict__ out, int N) {
    __shared__ float pooled[128];
    __shared__ float z[64];
    int t = threadIdx.x;
    if (t < 64) pooled[t] = (float)(g_pool_sum[t] / (double)N);
    else        pooled[t] = __int_as_float(g_pool_max[t - 64]);
    __syncthreads();
    if (t < 64) {
        float acc = bc1[t];
        for (int i = 0; i < 128; i++) acc += pooled[i] * Wc1[i * 64 + t];
        z[t] = fmaxf(acc, 0.f);
    }
    __syncthreads();
    if (t < 2) {
        float acc = bc2[t];
        for (int j = 0; j < 64; j++) acc += z[j] * Wc2[j * 2 + t];
        out[t] = acc;
    }
}

// ---------------- launch ----------------
static inline int cdiv(long long a, long long b) { return (int)((a + b - 1) / b); }

extern "C" void kernel_launch(void* const* d_in, const int* in_sizes, int n_in,
                              void* d_out, int out_size) {
    const float* x     = (const float*)d_in[0];
    const void*  ei    = d_in[1];
    const float* W0    = (const float*)d_in[2];
    const float* b0    = (const float*)d_in[3];
    const float* asrc0 = (const float*)d_in[4];
    const float* adst0 = (const float*)d_in[5];
    const float* g0    = (const float*)d_in[6];
    const float* be0   = (const float*)d_in[7];
    const float* W1    = (const float*)d_in[8];
    const float* b1    = (const float*)d_in[9];
    const float* asrc1 = (const float*)d_in[10];
    const float* adst1 = (const float*)d_in[11];
    const float* g1    = (const float*)d_in[12];
    const float* be1   = (const float*)d_in[13];
    const float* W2    = (const float*)d_in[14];
    const float* b2    = (const float*)d_in[15];
    const float* asrc2 = (const float*)d_in[16];
    const float* adst2 = (const float*)d_in[17];
    const float* g2    = (const float*)d_in[18];
    const float* be2   = (const float*)d_in[19];
    const float* Wc1   = (const float*)d_in[20];
    const float* bc1   = (const float*)d_in[21];
    const float* Wc2   = (const float*)d_in[22];
    const float* bc2   = (const float*)d_in[23];

    int N  = in_sizes[0] / 128;
    int E  = in_sizes[1] / 2;
    int ET = E + N;
    float invN = 1.0f / (float)N;

    float* ph = nullptr;
    __nv_bfloat16 *pAh = nullptr, *pAl = nullptr, *pBh = nullptr, *pBl = nullptr;
    cudaGetSymbolAddress((void**)&ph,  g_h);
    cudaGetSymbolAddress((void**)&pAh, g_Ah);
    cudaGetSymbolAddress((void**)&pAl, g_Al);
    cudaGetSymbolAddress((void**)&pBh, g_Bh);
    cudaGetSymbolAddress((void**)&pBl, g_Bl);

    int gtiles = cdiv(N, 128);
    int nb = cdiv(N, 256);

    // layer 0 front (hmma as 4th launch for ncu capture window)
    zero_sd<<<cdiv(N * 4, 256), 256>>>(N * 4);
    conv_split<<<2048, 256>>>(x, pAh, pAl, (size_t)N * 128);
    conv_w<<<cdiv(128 * 256, 256), 256>>>(W0, pBh, pBl, 128, 256);
    hmma_gemm<128><<<dim3(2, gtiles), 256>>>(pAh, pAl, pBh, pBl, ph, N, 128, 256, 4, asrc0, adst0);

    // CSR build (reused by all 3 layers)
    detect_kernel<<<1, 32>>>(ei);
    csr_zero<<<cdiv(N, 256), 256>>>(N);
    csr_hist<<<cdiv(ET, 256), 256>>>(ei, E, ET);
    scan1<<<nb, 256>>>(N);
    scan2<<<1, 256>>>(nb);
    scan3<<<nb, 256>>>(N, ET);
    csr_scatter<<<cdiv(ET, 256), 256>>>(ei, E, ET);

    // layer 0 rest
    gat_agg<4><<<cdiv((long long)N * 32, 256), 256>>>(N);
    bn_init<<<1, 256>>>();
    bn_stats<<<512, 256>>>(b0, 256, N);
    bn_final<<<1, 256>>>(g0, be0, 256, invN);
    bn_apply_split<<<2048, 256>>>(b0, 256, N * 256, pAh, pAl);

    // layer 1
    zero_sd<<<cdiv(N * 4, 256), 256>>>(N * 4);
    conv_w<<<cdiv(256 * 256, 256), 256>>>(W1, pBh, pBl, 256, 256);
    hmma_gemm<128><<<dim3(2, gtiles), 256>>>(pAh, pAl, pBh, pBl, ph, N, 256, 256, 4, asrc1, adst1);
    gat_agg<4><<<cdiv((long long)N * 32, 256), 256>>>(N);
    bn_init<<<1, 256>>>();
    bn_stats<<<512, 256>>>(b1, 256, N);
    bn_final<<<1, 256>>>(g1, be1, 256, invN);
    bn_apply_split<<<2048, 256>>>(b1, 256, N * 256, pAh, pAl);

    // layer 2
    zero_sd<<<cdiv(N, 256), 256>>>(N);
    conv_w<<<cdiv(256 * 64, 256), 256>>>(W2, pBh, pBl, 256, 64);
    hmma_gemm<64><<<dim3(1, gtiles), 256>>>(pAh, pAl, pBh, pBl, ph, N, 256, 64, 1, asrc2, adst2);
    gat_agg<1><<<cdiv((long long)N * 32, 256), 256>>>(N);
    bn_init<<<1, 256>>>();
    bn_stats<<<512, 256>>>(b2, 64, N);
    bn_final<<<1, 256>>>(g2, be2, 64, invN);
    pool_init<<<1, 64>>>();
    bn_apply_pool<<<2048, 256>>>(b2, N * 64);

    // classifier
    classifier<<<1, 128>>>(Wc1, bc1, Wc2, bc2, (float*)d_out, N);
}

// round 10
// speedup vs baseline: 2.0566x; 1.0199x over previous
#include <cuda_runtime.h>
#include <cuda_bf16.h>
#include <math.h>
#include <stdint.h>

// ---------------- problem constants ----------------
#define NMAX   50000
#define EMAX   800000
#define ETMAX  (EMAX + NMAX)
#define WD     256
#define HDIM   64

// ---------------- scratch ----------------
__device__ float  g_h  [(size_t)NMAX * WD];
__device__ float  g_out[(size_t)NMAX * WD];
__device__ float  g_s  [NMAX * 4];
__device__ float  g_d  [NMAX * 4];
__device__ double g_bnsum[WD];
__device__ double g_bnsq [WD];
__device__ float  g_scale[WD];
__device__ float  g_shift[WD];
__device__ double g_pool_sum[HDIM];
__device__ int    g_pool_max[HDIM];
__device__ int    g_is64;
__device__ int    g_deg   [NMAX];
__device__ int    g_cursor[NMAX];
__device__ int    g_rowptr[NMAX + 1];
__device__ int    g_csr   [ETMAX];
__device__ int    g_bsum[256];
__device__ int    g_boff[256];
__device__ __nv_bfloat16 g_Ah[(size_t)NMAX * WD];
__device__ __nv_bfloat16 g_Al[(size_t)NMAX * WD];
__device__ __nv_bfloat16 g_Bh[WD * WD];
__device__ __nv_bfloat16 g_Bl[WD * WD];

// ---------------- edge helpers ----------------
__device__ __forceinline__ void get_edge(const void* ei, int e, int E, int& s, int& d) {
    if (e >= E) { s = d = e - E; return; }
    if (g_is64) {
        const long long* p = (const long long*)ei;
        s = (int)p[e]; d = (int)p[(size_t)E + e];
    } else {
        const int* p = (const int*)ei;
        s = p[e]; d = p[E + e];
    }
}

__global__ void detect_kernel(const void* ei) {
    if (threadIdx.x == 0 && blockIdx.x == 0) {
        const unsigned* w = (const unsigned*)ei;
        int is64 = 1;
        for (int i = 0; i < 8; i++)
            if (w[2 * i + 1] != 0u) is64 = 0;
        g_is64 = is64;
    }
}

// ---------------- CSR build ----------------
__global__ void csr_zero(int N) {
    int i = blockIdx.x * blockDim.x + threadIdx.x;
    if (i < N) { g_deg[i] = 0; g_cursor[i] = 0; }
}
__global__ void csr_hist(const void* __restrict__ ei, int E, int ET) {
    int e = blockIdx.x * blockDim.x + threadIdx.x;
    if (e >= ET) return;
    int s, d; get_edge(ei, e, E, s, d);
    atomicAdd(&g_deg[d], 1);
}
__global__ void scan1(int N) {
    __shared__ int sh[256];
    int i = blockIdx.x * 256 + threadIdx.x;
    int v = (i < N) ? g_deg[i] : 0;
    sh[threadIdx.x] = v;
    __syncthreads();
    for (int o = 128; o; o >>= 1) {
        if (threadIdx.x < o) sh[threadIdx.x] += sh[threadIdx.x + o];
        __syncthreads();
    }
    if (threadIdx.x == 0) g_bsum[blockIdx.x] = sh[0];
}
__global__ void scan2(int nb) {
    __shared__ int sh[256];
    int t = threadIdx.x;
    int v = (t < nb) ? g_bsum[t] : 0;
    sh[t] = v;
    __syncthreads();
    for (int o = 1; o < 256; o <<= 1) {
        int u = (t >= o) ? sh[t - o] : 0;
        __syncthreads();
        sh[t] += u;
        __syncthreads();
    }
    g_boff[t] = sh[t] - v;
}
__global__ void scan3(int N, int ET) {
    __shared__ int sh[256];
    int t = threadIdx.x;
    int i = blockIdx.x * 256 + t;
    int v = (i < N) ? g_deg[i] : 0;
    sh[t] = v;
    __syncthreads();
    for (int o = 1; o < 256; o <<= 1) {
        int u = (t >= o) ? sh[t - o] : 0;
        __syncthreads();
        sh[t] += u;
        __syncthreads();
    }
    if (i < N) g_rowptr[i] = g_boff[blockIdx.x] + sh[t] - v;
    if (blockIdx.x == 0 && t == 0) g_rowptr[N] = ET;
}
__global__ void csr_scatter(const void* __restrict__ ei, int E, int ET) {
    int e = blockIdx.x * blockDim.x + threadIdx.x;
    if (e >= ET) return;
    int s, d; get_edge(ei, e, E, s, d);
    int pos = g_rowptr[d] + atomicAdd(&g_cursor[d], 1);
    g_csr[pos] = s;
}

// ---------------- fp32 -> bf16 hi/lo splits ----------------
__global__ void conv_split(const float* __restrict__ src, __nv_bfloat16* __restrict__ hi,
                           __nv_bfloat16* __restrict__ lo, size_t n) {
    size_t stride = (size_t)gridDim.x * blockDim.x;
    for (size_t i = (size_t)blockIdx.x * blockDim.x + threadIdx.x; i < n; i += stride) {
        float x = src[i];
        __nv_bfloat16 h = __float2bfloat16(x);
        hi[i] = h;
        lo[i] = __float2bfloat16(x - __bfloat162float(h));
    }
}
__global__ void conv_w(const float* __restrict__ W, __nv_bfloat16* __restrict__ hi,
                       __nv_bfloat16* __restrict__ lo, int K, int NC) {
    int i = blockIdx.x * blockDim.x + threadIdx.x;
    if (i >= K * NC) return;
    int k = i / NC, n = i % NC;
    float x = W[i];
    __nv_bfloat16 h = __float2bfloat16(x);
    hi[(size_t)n * K + k] = h;
    lo[(size_t)n * K + k] = __float2bfloat16(x - __bfloat162float(h));
}

__global__ void zero_sd(int nh) {
    int i = blockIdx.x * blockDim.x + threadIdx.x;
    if (i < nh) { g_s[i] = 0.f; g_d[i] = 0.f; }
}

// ---------------- mma.sync helpers ----------------
__device__ __forceinline__ void ldsm_x4(uint32_t* r, uint32_t addr) {
    asm volatile("ldmatrix.sync.aligned.m8n8.x4.shared.b16 {%0,%1,%2,%3}, [%4];"
                 : "=r"(r[0]), "=r"(r[1]), "=r"(r[2]), "=r"(r[3]) : "r"(addr));
}
__device__ __forceinline__ void mma_bf16(float* c, const uint32_t* a, const uint32_t* b) {
    asm volatile("mma.sync.aligned.m16n8k16.row.col.f32.bf16.bf16.f32 "
                 "{%0,%1,%2,%3}, {%4,%5,%6,%7}, {%8,%9}, {%0,%1,%2,%3};"
                 : "+f"(c[0]), "+f"(c[1]), "+f"(c[2]), "+f"(c[3])
                 : "r"(a[0]), "r"(a[1]), "r"(a[2]), "r"(a[3]), "r"(b[0]), "r"(b[1]));
}

// ---------------- HMMA GEMM, 2 CTAs/SM, fused s/d epilogue ----------------
// C = A @ W ; A = Ah+Al, B = Bh+Bl; drop Al*Bl. Products issued in three
// independent sweeps over 16 accumulators (no RAW chains on the tensor pipe).
template <int BN>
__global__ __launch_bounds__(256, 2)
void hmma_gemm(const __nv_bfloat16* __restrict__ Ah, const __nv_bfloat16* __restrict__ Al,
               const __nv_bfloat16* __restrict__ Bh, const __nv_bfloat16* __restrict__ Bl,
               float* __restrict__ Cout, int M, int K, int NC, int H,
               const float* __restrict__ asrc, const float* __restrict__ adst) {
    constexpr int WN  = BN / 32;
    constexpr int WM  = 8 / WN;
    constexpr int WTM = 128 / WM;
    constexpr int MF  = WTM / 16;
    constexpr int AST = 40;
    constexpr int NB  = BN / 64;

    __shared__ __nv_bfloat16 sAh[128 * AST];
    __shared__ __nv_bfloat16 sAl[128 * AST];
    __shared__ __nv_bfloat16 sBh[BN * AST];
    __shared__ __nv_bfloat16 sBl[BN * AST];

    const int tid  = threadIdx.x;
    const int wid  = tid >> 5, lane = tid & 31;
    const int row0 = blockIdx.y * 128;
    const int bn0  = blockIdx.x * BN;
    const int warpM = wid % WM, warpN = wid / WM;
    const int m0 = warpM * WTM;
    const int n0 = warpN * 32;

    float acc[MF][4][4];
#pragma unroll
    for (int i = 0; i < MF; i++)
#pragma unroll
        for (int j = 0; j < 4; j++)
#pragma unroll
            for (int k = 0; k < 4; k++) acc[i][j][k] = 0.f;

    const int nch = K >> 5;

    const uint32_t bAh = (uint32_t)__cvta_generic_to_shared(sAh);
    const uint32_t bAl = (uint32_t)__cvta_generic_to_shared(sAl);
    const uint32_t bBh = (uint32_t)__cvta_generic_to_shared(sBh);
    const uint32_t bBl = (uint32_t)__cvta_generic_to_shared(sBl);

    for (int c = 0; c < nch; c++) {
        const int k0 = c * 32;
        __syncthreads();
#pragma unroll
        for (int it = 0; it < 2; it++) {
            int i = tid + it * 256;
            int r = i >> 2, seg = i & 3;
            int gr = row0 + r; if (gr >= M) gr = M - 1;
            size_t off = (size_t)gr * K + k0 + seg * 8;
            *(uint4*)&sAh[r * AST + seg * 8] = *(const uint4*)(Ah + off);
            *(uint4*)&sAl[r * AST + seg * 8] = *(const uint4*)(Al + off);
        }
#pragma unroll
        for (int it = 0; it < NB; it++) {
            int i = tid + it * 256;
            int r = i >> 2, seg = i & 3;
            size_t off = (size_t)(bn0 + r) * K + k0 + seg * 8;
            *(uint4*)&sBh[r * AST + seg * 8] = *(const uint4*)(Bh + off);
            *(uint4*)&sBl[r * AST + seg * 8] = *(const uint4*)(Bl + off);
        }
        __syncthreads();

#pragma unroll
        for (int ks = 0; ks < 2; ks++) {
            const int kc = ks * 16;
            uint32_t afh[MF][4], afl[MF][4], bfh[2][4], bfl[2][4];
            int ar = (lane & 15), ak = kc + ((lane >> 4) << 3);
#pragma unroll
            for (int fi = 0; fi < MF; fi++) {
                uint32_t o = (uint32_t)((m0 + fi * 16 + ar) * AST + ak) * 2;
                ldsm_x4(afh[fi], bAh + o);
                ldsm_x4(afl[fi], bAl + o);
            }
            int br = (lane & 7) + ((lane >> 4) << 3), bk = kc + (lane & 8);
#pragma unroll
            for (int g = 0; g < 2; g++) {
                uint32_t o = (uint32_t)((n0 + g * 16 + br) * AST + bk) * 2;
                ldsm_x4(bfh[g], bBh + o);
                ldsm_x4(bfl[g], bBl + o);
            }
            // three independent sweeps -> 16 accumulators between RAW revisits
#pragma unroll
            for (int fi = 0; fi < MF; fi++)
#pragma unroll
                for (int ni = 0; ni < 4; ni++)
                    mma_bf16(acc[fi][ni], afh[fi], &bfh[ni >> 1][(ni & 1) * 2]);
#pragma unroll
            for (int fi = 0; fi < MF; fi++)
#pragma unroll
                for (int ni = 0; ni < 4; ni++)
                    mma_bf16(acc[fi][ni], afh[fi], &bfl[ni >> 1][(ni & 1) * 2]);
#pragma unroll
            for (int fi = 0; fi < MF; fi++)
#pragma unroll
                for (int ni = 0; ni < 4; ni++)
                    mma_bf16(acc[fi][ni], afl[fi], &bfh[ni >> 1][(ni & 1) * 2]);
        }
    }

    // ---- epilogue: store C and fused s/d partial dot products ----
    const int crow = lane >> 2, ccol = (lane & 3) * 2;
    const int head = (bn0 + n0) >> 6;
    float2 avs[4], avd[4];
#pragma unroll
    for (int ni = 0; ni < 4; ni++) {
        int cc = bn0 + n0 + ni * 8 + ccol;
        avs[ni] = *(const float2*)&asrc[cc];
        avd[ni] = *(const float2*)&adst[cc];
    }
#pragma unroll
    for (int fi = 0; fi < MF; fi++) {
        int r_lo = row0 + m0 + fi * 16 + crow;
        int r_hi = r_lo + 8;
        float sl = 0.f, dl = 0.f, sh = 0.f, dh = 0.f;
#pragma unroll
        for (int ni = 0; ni < 4; ni++) {
            int c = bn0 + n0 + ni * 8 + ccol;
            if (r_lo < M)
                *(float2*)&Cout[(size_t)r_lo * NC + c] = make_float2(acc[fi][ni][0], acc[fi][ni][1]);
            if (r_hi < M)
                *(float2*)&Cout[(size_t)r_hi * NC + c] = make_float2(acc[fi][ni][2], acc[fi][ni][3]);
            sl += acc[fi][ni][0] * avs[ni].x + acc[fi][ni][1] * avs[ni].y;
            dl += acc[fi][ni][0] * avd[ni].x + acc[fi][ni][1] * avd[ni].y;
            sh += acc[fi][ni][2] * avs[ni].x + acc[fi][ni][3] * avs[ni].y;
            dh += acc[fi][ni][2] * avd[ni].x + acc[fi][ni][3] * avd[ni].y;
        }
#pragma unroll
        for (int o = 1; o <= 2; o <<= 1) {
            sl += __shfl_xor_sync(0xffffffffu, sl, o);
            dl += __shfl_xor_sync(0xffffffffu, dl, o);
            sh += __shfl_xor_sync(0xffffffffu, sh, o);
            dh += __shfl_xor_sync(0xffffffffu, dh, o);
        }
        if ((lane & 3) == 0) {
            if (r_lo < M) {
                atomicAdd(&g_s[r_lo * H + head], sl);
                atomicAdd(&g_d[r_lo * H + head], dl);
            }
            if (r_hi < M) {
                atomicAdd(&g_s[r_hi * H + head], sh);
                atomicAdd(&g_d[r_hi * H + head], dh);
            }
        }
    }
}

// select from a compile-time register array with runtime index (no spill)
template <int H>
__device__ __forceinline__ float sel(const float (&a)[H], int h) {
    float r = a[0];
#pragma unroll
    for (int i = 1; i < H; i++) r = (h == i) ? a[i] : r;
    return r;
}

// ---------------- fused segment softmax + aggregation: warp per destination ----------------
template <int H>
__global__ __launch_bounds__(256) void gat_agg(int N) {
    const int T  = H * 64;
    const int CH = T / 32;
    int warp = (blockIdx.x * blockDim.x + threadIdx.x) >> 5;
    int lane = threadIdx.x & 31;
    if (warp >= N) return;
    int n = warp;

    float sdd[H];
#pragma unroll
    for (int h = 0; h < H; h++) sdd[h] = g_d[n * H + h];

    int r0 = g_rowptr[n], r1 = g_rowptr[n + 1];
    int deg = r1 - r0;
    const int myh = (lane * CH) >> 6;

    float acc[CH];
#pragma unroll
    for (int c = 0; c < CH; c++) acc[c] = 0.f;

    if (deg <= 32) {
        // ---------- fast path: lane owns (at most) one incoming edge ----------
        bool has = lane < deg;
        int s = has ? g_csr[r0 + lane] : 0;
        float ex[H];
#pragma unroll
        for (int h = 0; h < H; h++) {
            float t = g_s[s * H + h] + sdd[h];
            t = t > 0.f ? t : 0.2f * t;
            ex[h] = has ? t : -1e30f;
        }
        // warp max per head
#pragma unroll
        for (int h = 0; h < H; h++) {
            float m = ex[h];
            for (int o = 16; o; o >>= 1) m = fmaxf(m, __shfl_xor_sync(0xffffffffu, m, o));
            ex[h] = has ? expf(ex[h] - m) : 0.f;
        }
        // warp denom + normalize: ex[h] becomes alpha of this lane's edge, head h
#pragma unroll
        for (int h = 0; h < H; h++) {
            float dsum = ex[h];
            for (int o = 16; o; o >>= 1) dsum += __shfl_xor_sync(0xffffffffu, dsum, o);
            ex[h] *= 1.f / (dsum + 1e-16f);
        }
        // aggregation
        if (H == 4) {
            for (int b0 = 0; b0 < deg; b0 += 8) {
                int src_l = (b0 + (lane >> 2)) & 31;
                float tmp[4];
#pragma unroll
                for (int h = 0; h < 4; h++)
                    tmp[h] = __shfl_sync(0xffffffffu, ex[h], src_l);
                float av = sel<4>(tmp, lane & 3);   // alpha(edge b0+(lane>>2), head lane&3)
                int ce = deg - b0; if (ce > 8) ce = 8;
                for (int e = 0; e < ce; e++) {
                    int ss  = __shfl_sync(0xffffffffu, s, b0 + e);
                    float a = __shfl_sync(0xffffffffu, av, (e << 2) | myh);
                    const float* hp = &g_h[(size_t)ss * 256 + lane * 8];
                    float4 h0 = *(const float4*)hp;
                    float4 h1 = *(const float4*)(hp + 4);
                    acc[0] += h0.x * a; acc[1] += h0.y * a;
                    acc[2] += h0.z * a; acc[3] += h0.w * a;
                    acc[4] += h1.x * a; acc[5] += h1.y * a;
                    acc[6] += h1.z * a; acc[7] += h1.w * a;
                }
            }
        } else {
            for (int e = 0; e < deg; e++) {
                int ss  = __shfl_sync(0xffffffffu, s, e);
                float a = __shfl_sync(0xffffffffu, ex[0], e);
                const float* hp = &g_h[(size_t)ss * 64 + lane * 2];
                float2 h0 = *(const float2*)hp;
                acc[0] += h0.x * a; acc[1] += h0.y * a;
            }
        }
    } else {
        // ---------- general path (deg > 32) ----------
        float mx[H];
#pragma unroll
        for (int h = 0; h < H; h++) mx[h] = -1e30f;
        for (int i = r0 + lane; i < r1; i += 32) {
            int s = g_csr[i];
#pragma unroll
            for (int h = 0; h < H; h++) {
                float v = g_s[s * H + h] + sdd[h];
                v = v > 0.f ? v : 0.2f * v;
                mx[h] = fmaxf(mx[h], v);
            }
        }
#pragma unroll
        for (int h = 0; h < H; h++)
            for (int o = 16; o; o >>= 1)
                mx[h] = fmaxf(mx[h], __shfl_xor_sync(0xffffffffu, mx[h], o));

        float den[H];
#pragma unroll
        for (int h = 0; h < H; h++) den[h] = 0.f;
        for (int i = r0 + lane; i < r1; i += 32) {
            int s = g_csr[i];
#pragma unroll
            for (int h = 0; h < H; h++) {
                float v = g_s[s * H + h] + sdd[h];
                v = v > 0.f ? v : 0.2f * v;
                den[h] += expf(v - mx[h]);
            }
        }
#pragma unroll
        for (int h = 0; h < H; h++) {
            for (int o = 16; o; o >>= 1)
                den[h] += __shfl_xor_sync(0xffffffffu, den[h], o);
            den[h] = 1.f / (den[h] + 1e-16f);
        }

        const int ah = (H == 4) ? (lane & 3) : 0;
        const int ae = (H == 4) ? (lane >> 2) : lane;
        const float amx  = sel<H>(mx, ah);
        const float aden = sel<H>(den, ah);
        const float asd  = sel<H>(sdd, ah);
        const int EB = (H == 4) ? 8 : 32;

        for (int base = r0; base < r1; base += 32) {
            int idx = base + lane;
            int srcs = (idx < r1) ? g_csr[idx] : 0;
            int cnt = r1 - base; if (cnt > 32) cnt = 32;
            for (int b0 = 0; b0 < cnt; b0 += EB) {
                int sl = __shfl_sync(0xffffffffu, srcs, (b0 + ae) & 31);
                float v = g_s[sl * H + ah] + asd;
                v = v > 0.f ? v : 0.2f * v;
                float alpha = expf(v - amx) * aden;
                int ce = cnt - b0; if (ce > EB) ce = EB;
                for (int e = 0; e < ce; e++) {
                    int s  = __shfl_sync(0xffffffffu, srcs, b0 + e);
                    float a = (H == 4) ? __shfl_sync(0xffffffffu, alpha, (e << 2) | myh)
                                       : __shfl_sync(0xffffffffu, alpha, e);
                    const float* hp = &g_h[(size_t)s * T + lane * CH];
                    if (CH == 8) {
                        float4 h0 = *(const float4*)hp;
                        float4 h1 = *(const float4*)(hp + 4);
                        acc[0] += h0.x * a; acc[1] += h0.y * a;
                        acc[2] += h0.z * a; acc[3] += h0.w * a;
                        acc[4] += h1.x * a; acc[5] += h1.y * a;
                        acc[6] += h1.z * a; acc[7] += h1.w * a;
                    } else {
                        float2 h0 = *(const float2*)hp;
                        acc[0] += h0.x * a; acc[1] += h0.y * a;
                    }
                }
            }
        }
    }

    float* op = &g_out[(size_t)n * T + lane * CH];
    if (CH == 8) {
        *(float4*)op       = make_float4(acc[0], acc[1], acc[2], acc[3]);
        *(float4*)(op + 4) = make_float4(acc[4], acc[5], acc[6], acc[7]);
    } else {
        *(float2*)op = make_float2(acc[0], acc[1]);
    }
}

// ---------------- batchnorm ----------------
__global__ void bn_init() {
    int c = threadIdx.x;
    g_bnsum[c] = 0.0; g_bnsq[c] = 0.0;
}
__global__ void bn_stats(const float* __restrict__ bias, int C, int N) {
    int rpb = 256 / C;
    int c  = threadIdx.x % C;
    int r0 = blockIdx.x * rpb + threadIdx.x / C;
    double s = 0.0, q = 0.0;
    for (int r = r0; r < N; r += gridDim.x * rpb) {
        float v = g_out[(size_t)r * C + c] + bias[c];
        s += v; q += (double)v * v;
    }
    atomicAdd(&g_bnsum[c], s);
    atomicAdd(&g_bnsq[c], q);
}
__global__ void bn_final(const float* __restrict__ gamma, const float* __restrict__ beta,
                         int C, float inv_n) {
    int c = threadIdx.x;
    if (c >= C) return;
    float mu  = (float)(g_bnsum[c] * inv_n);
    float var = (float)(g_bnsq[c] * inv_n) - mu * mu;
    float sc  = gamma[c] * rsqrtf(var + 1e-5f);
    g_scale[c] = sc;
    g_shift[c] = beta[c] - sc * mu;
}
__global__ void bn_apply_split(const float* __restrict__ bias, int C, int total,
                               __nv_bfloat16* __restrict__ hi, __nv_bfloat16* __restrict__ lo) {
    int stride = gridDim.x * blockDim.x;
    for (int i = blockIdx.x * blockDim.x + threadIdx.x; i < total; i += stride) {
        int c = i & (C - 1);
        float v = g_out[i] + bias[c];
        v = g_scale[c] * v + g_shift[c];
        v = fmaxf(v, 0.f);
        __nv_bfloat16 h = __float2bfloat16(v);
        hi[i] = h;
        lo[i] = __float2bfloat16(v - __bfloat162float(h));
    }
}
__global__ void bn_apply_pool(const float* __restrict__ bias, int total) {
    __shared__ float ssum[64];
    __shared__ int   smax[64];
    int t = threadIdx.x;
    if (t < 64) { ssum[t] = 0.f; smax[t] = 0; }
    __syncthreads();
    int stride = gridDim.x * blockDim.x;
    float lsum = 0.f, lmax = 0.f;
    int c = (blockIdx.x * blockDim.x + t) & 63;
    for (int i = blockIdx.x * blockDim.x + t; i < total; i += stride) {
        float v = g_out[i] + bias[c];
        v = g_scale[c] * v + g_shift[c];
        v = fmaxf(v, 0.f);
        g_out[i] = v;
        lsum += v; lmax = fmaxf(lmax, v);
    }
    atomicAdd(&ssum[t & 63], lsum);
    atomicMax(&smax[t & 63], __float_as_int(lmax));
    __syncthreads();
    if (t < 64) {
        atomicAdd(&g_pool_sum[t], (double)ssum[t]);
        atomicMax(&g_pool_max[t], smax[t]);
    }
}

// ---------------- pooling init + classifier ----------------
__global__ void pool_init() {
    int c = threadIdx.x;
    g_pool_sum[c] = 0.0;
    g_pool_max[c] = 0;
}
__global__ void classifier(const float* __restrict__ Wc1, const float* __restrict__ bc1,
                           const float* __restrict__ Wc2, const float* __restrict__ bc2,
                           float* __restrict__ out, int N) {
    __shared__ float pooled[128];
    __shared__ float z[64];
    int t = threadIdx.x;
    if (t < 64) pooled[t] = (float)(g_pool_sum[t] / (double)N);
    else        pooled[t] = __int_as_float(g_pool_max[t - 64]);
    __syncthreads();
    if (t < 64) {
        float acc = bc1[t];
        for (int i = 0; i < 128; i++) acc += pooled[i] * Wc1[i * 64 + t];
        z[t] = fmaxf(acc, 0.f);
    }
    __syncthreads();
    if (t < 2) {
        float acc = bc2[t];
        for (int j = 0; j < 64; j++) acc += z[j] * Wc2[j * 2 + t];
        out[t] = acc;
    }
}

// ---------------- launch ----------------
static inline int cdiv(long long a, long long b) { return (int)((a + b - 1) / b); }

extern "C" void kernel_launch(void* const* d_in, const int* in_sizes, int n_in,
                              void* d_out, int out_size) {
    const float* x     = (const float*)d_in[0];
    const void*  ei    = d_in[1];
    const float* W0    = (const float*)d_in[2];
    const float* b0    = (const float*)d_in[3];
    const float* asrc0 = (const float*)d_in[4];
    const float* adst0 = (const float*)d_in[5];
    const float* g0    = (const float*)d_in[6];
    const float* be0   = (const float*)d_in[7];
    const float* W1    = (const float*)d_in[8];
    const float* b1    = (const float*)d_in[9];
    const float* asrc1 = (const float*)d_in[10];
    const float* adst1 = (const float*)d_in[11];
    const float* g1    = (const float*)d_in[12];
    const float* be1   = (const float*)d_in[13];
    const float* W2    = (const float*)d_in[14];
    const float* b2    = (const float*)d_in[15];
    const float* asrc2 = (const float*)d_in[16];
    const float* adst2 = (const float*)d_in[17];
    const float* g2    = (const float*)d_in[18];
    const float* be2   = (const float*)d_in[19];
    const float* Wc1   = (const float*)d_in[20];
    const float* bc1   = (const float*)d_in[21];
    const float* Wc2   = (const float*)d_in[22];
    const float* bc2   = (const float*)d_in[23];

    int N  = in_sizes[0] / 128;
    int E  = in_sizes[1] / 2;
    int ET = E + N;
    float invN = 1.0f / (float)N;

    float* ph = nullptr;
    __nv_bfloat16 *pAh = nullptr, *pAl = nullptr, *pBh = nullptr, *pBl = nullptr;
    cudaGetSymbolAddress((void**)&ph,  g_h);
    cudaGetSymbolAddress((void**)&pAh, g_Ah);
    cudaGetSymbolAddress((void**)&pAl, g_Al);
    cudaGetSymbolAddress((void**)&pBh, g_Bh);
    cudaGetSymbolAddress((void**)&pBl, g_Bl);

    int gtiles = cdiv(N, 128);
    int nb = cdiv(N, 256);

    // layer 0 front (hmma as 4th launch for ncu capture window)
    zero_sd<<<cdiv(N * 4, 256), 256>>>(N * 4);
    conv_split<<<2048, 256>>>(x, pAh, pAl, (size_t)N * 128);
    conv_w<<<cdiv(128 * 256, 256), 256>>>(W0, pBh, pBl, 128, 256);
    hmma_gemm<128><<<dim3(2, gtiles), 256>>>(pAh, pAl, pBh, pBl, ph, N, 128, 256, 4, asrc0, adst0);

    // CSR build (reused by all 3 layers)
    detect_kernel<<<1, 32>>>(ei);
    csr_zero<<<cdiv(N, 256), 256>>>(N);
    csr_hist<<<cdiv(ET, 256), 256>>>(ei, E, ET);
    scan1<<<nb, 256>>>(N);
    scan2<<<1, 256>>>(nb);
    scan3<<<nb, 256>>>(N, ET);
    csr_scatter<<<cdiv(ET, 256), 256>>>(ei, E, ET);

    // layer 0 rest
    gat_agg<4><<<cdiv((long long)N * 32, 256), 256>>>(N);
    bn_init<<<1, 256>>>();
    bn_stats<<<512, 256>>>(b0, 256, N);
    bn_final<<<1, 256>>>(g0, be0, 256, invN);
    bn_apply_split<<<2048, 256>>>(b0, 256, N * 256, pAh, pAl);

    // layer 1
    zero_sd<<<cdiv(N * 4, 256), 256>>>(N * 4);
    conv_w<<<cdiv(256 * 256, 256), 256>>>(W1, pBh, pBl, 256, 256);
    hmma_gemm<128><<<dim3(2, gtiles), 256>>>(pAh, pAl, pBh, pBl, ph, N, 256, 256, 4, asrc1, adst1);
    gat_agg<4><<<cdiv((long long)N * 32, 256), 256>>>(N);
    bn_init<<<1, 256>>>();
    bn_stats<<<512, 256>>>(b1, 256, N);
    bn_final<<<1, 256>>>(g1, be1, 256, invN);
    bn_apply_split<<<2048, 256>>>(b1, 256, N * 256, pAh, pAl);

    // layer 2
    zero_sd<<<cdiv(N, 256), 256>>>(N);
    conv_w<<<cdiv(256 * 64, 256), 256>>>(W2, pBh, pBl, 256, 64);
    hmma_gemm<64><<<dim3(1, gtiles), 256>>>(pAh, pAl, pBh, pBl, ph, N, 256, 64, 1, asrc2, adst2);
    gat_agg<1><<<cdiv((long long)N * 32, 256), 256>>>(N);
    bn_init<<<1, 256>>>();
    bn_stats<<<512, 256>>>(b2, 64, N);
    bn_final<<<1, 256>>>(g2, be2, 64, invN);
    pool_init<<<1, 64>>>();
    bn_apply_pool<<<2048, 256>>>(b2, N * 64);

    // classifier
    classifier<<<1, 128>>>(Wc1, bc1, Wc2, bc2, (float*)d_out, N);
}